// round 3
// baseline (speedup 1.0000x reference)
#include <cuda_runtime.h>
#include <math.h>

#define T_LEN 1440
#define B_LEN 2048
#define N_RC  5
#define L_CH  16
#define N_CH  90      // 1440/16
#define WCH   3       // warm chunks (t < 48)

typedef unsigned long long u64;

__device__ float g_tzz[T_LEN * B_LEN];     // zero-state Tz trajectory
__device__ float g_d [N_CH * 6 * B_LEN];   // per-chunk affine offsets
__device__ float g_cs[N_CH * 6 * B_LEN];   // chunk-start states
__device__ float g_A16[36];                // A^16 row-major
__device__ float g_r0p[17 * 6];            // row0(A^n), n=1..16
__device__ float g_e[16 * 5];              // g*ri_i*m_i^s
__device__ float g_m16[5];                 // m_i^16

__device__ __forceinline__ float sp(float x) {
    if (x > 20.f)  return x;
    if (x < -20.f) return expf(x);
    return log1pf(expf(x));
}

__device__ __forceinline__ u64 pack2(float lo, float hi) {
    u64 r; asm("mov.b64 %0,{%1,%2};" : "=l"(r) : "f"(lo), "f"(hi)); return r;
}
__device__ __forceinline__ void unpack2(u64 v, float& lo, float& hi) {
    asm("mov.b64 {%0,%1},%2;" : "=f"(lo), "=f"(hi) : "l"(v));
}
__device__ __forceinline__ u64 fma2(u64 a, u64 b, u64 c) {
    u64 d; asm("fma.rn.f32x2 %0,%1,%2,%3;" : "=l"(d) : "l"(a), "l"(b), "l"(c)); return d;
}
__device__ __forceinline__ u64 add2(u64 a, u64 b) {
    u64 d; asm("add.rn.f32x2 %0,%1,%2;" : "=l"(d) : "l"(a), "l"(b)); return d;
}

struct P { float ri[N_RC], m[N_RC], kta[N_RC], ks[N_RC], alpha, g, gw; };

__device__ __forceinline__ void loadP(P& p,
    const float* rcR, const float* rcC, const float* winR,
    const float* paw, const float* par, const float* pcz)
{
    const float aw = 0.5f * sp(paw[0]);
    const float ar = 0.5f * sp(par[0]);
    float Rsum = 0.f;
    #pragma unroll
    for (int i = 0; i < N_RC; i++) {
        const float r = sp(rcR[i]) * 0.1f;
        const float c = sp(rcC[i]) * 1e-5f;
        const float a = (i < 4) ? aw : ar;
        p.ri[i] = r; Rsum += r;
        const float cd = c * 900.f;
        p.kta[i] = cd * r;
        p.m[i]   = 1.f - 2.f * cd * r;
        p.ks[i]  = cd * a;
    }
    const float win = (sp(winR[0]) + sp(winR[1])) * 0.5f;
    const float cz  = sp(pcz[0]) * 1e-5f;
    p.g     = cz * 900.f;
    p.alpha = 1.f - p.g * (Rsum + win);
    p.gw    = p.g * win;
}

// homogeneous step (setup only)
__device__ __forceinline__ void hstep(const P& p, float x[6]) {
    float tz = x[0];
    float S = x[1] * p.ri[0];
    S = fmaf(x[2], p.ri[1], S);
    S = fmaf(x[3], p.ri[2], S);
    S = fmaf(x[4], p.ri[3], S);
    S = fmaf(x[5], p.ri[4], S);
    const float tznew = fmaf(p.alpha, tz, p.g * S);
    #pragma unroll
    for (int i = 0; i < N_RC; i++)
        x[1 + i] = fmaf(p.kta[i], tz, p.m[i] * x[1 + i]);
    x[0] = tznew;
}

// ---------------------------------------------------------------------------
// Setup: A^16, row0(A^n) n=1..16, e-table, m^16.  1 block of 32 threads.
// ---------------------------------------------------------------------------
__global__ void k_setup(
    const float* __restrict__ rcR, const float* __restrict__ rcC,
    const float* __restrict__ winR,
    const float* __restrict__ paw, const float* __restrict__ par,
    const float* __restrict__ pcz)
{
    const int j = threadIdx.x;
    P p; loadP(p, rcR, rcC, winR, paw, par, pcz);
    if (j < 6) {
        float x[6] = {0.f, 0.f, 0.f, 0.f, 0.f, 0.f};
        x[j] = 1.f;
        for (int n = 1; n <= L_CH; n++) {
            hstep(p, x);
            g_r0p[n * 6 + j] = x[0];
        }
        #pragma unroll
        for (int i = 0; i < 6; i++) g_A16[i * 6 + j] = x[i];
    } else if (j == 6) {
        float mp[N_RC];
        #pragma unroll
        for (int i = 0; i < N_RC; i++) mp[i] = 1.f;
        for (int s = 0; s < L_CH; s++) {
            #pragma unroll
            for (int i = 0; i < N_RC; i++) {
                g_e[s * 5 + i] = p.g * p.ri[i] * mp[i];
                mp[i] *= p.m[i];
            }
        }
        #pragma unroll
        for (int i = 0; i < N_RC; i++) g_m16[i] = mp[i];
    }
}

// ---------------------------------------------------------------------------
// Phase A (fused drives + zero-state replay). One thread = one (b, chunk).
// ---------------------------------------------------------------------------
template<bool WARM>
__global__ __launch_bounds__(128) void kA(
    const float* __restrict__ X,
    const float* __restrict__ rcR, const float* __restrict__ rcC,
    const float* __restrict__ winR,
    const float* __restrict__ W1, const float* __restrict__ B1,
    const float* __restrict__ W2, const float* __restrict__ B2,
    const float* __restrict__ pig, const float* __restrict__ phg,
    const float* __restrict__ pdg,
    const float* __restrict__ paw, const float* __restrict__ par,
    const float* __restrict__ pcz, int jbase)
{
    __shared__ __align__(16) u64 swab[64];  // [2h]=w1a dup, [2h+1]=w1b dup
    __shared__ __align__(16) u64 sbw2[64];  // [2h]=b1 dup,  [2h+1]=0.5*w2 dup
    const int tid = threadIdx.x;
    if (tid < 32) {
        const float wa = W1[2 * tid], wb = W1[2 * tid + 1];
        swab[2 * tid]     = pack2(wa, wa);
        swab[2 * tid + 1] = pack2(wb, wb);
        const float b1 = B1[tid], w2h = 0.5f * W2[tid];
        sbw2[2 * tid]     = pack2(b1, b1);
        sbw2[2 * tid + 1] = pack2(w2h, w2h);
    }
    const float gi  = 0.1f * sp(pig[0]);
    const float gh  = 0.1f * sp(phg[0]);
    const float gd  = 0.5f * sp(pdg[0]);
    const float g   = sp(pcz[0]) * 1e-5f * 900.f;
    const float win = (sp(winR[0]) + sp(winR[1])) * 0.5f;
    const float gw  = g * win;
    const float ggi = g * gi;
    const float b2v = B2[0];
    __syncthreads();

    const int j  = jbase + blockIdx.y;
    const int t0 = j * L_CH;
    const int b  = blockIdx.x * 128 + tid;
    const float* xb = X + (size_t)b * (T_LEN * 7) + (size_t)t0 * 7;

    float ta[16], so[16], u[16];
    u64 X0p[8], X1p[8], acc[8];
    const u64 b2_2 = pack2(b2v, b2v);

    #pragma unroll
    for (int pp = 0; pp < 8; pp++) {
        const float* e = xb + 14 * pp;
        const float ta0 = e[1],  so0 = e[2],  x00 = e[3],  x10 = e[4],  x20 = e[5],  hv0 = e[6];
        const float ta1 = e[8],  so1 = e[9],  x01 = e[10], x11 = e[11], x21 = e[12], hv1 = e[13];
        X0p[pp] = pack2(x00, x01);
        X1p[pp] = pack2(x10, x11);
        acc[pp] = b2_2;
        ta[2 * pp] = ta0; ta[2 * pp + 1] = ta1;
        so[2 * pp] = so0; so[2 * pp + 1] = so1;
        const float r0 = fmaf(gd, so0, fmaf(gh, hv0, gi * x20));
        const float r1 = fmaf(gd, so1, fmaf(gh, hv1, gi * x21));
        u[2 * pp]     = fmaf(gw, ta0, g * r0);
        u[2 * pp + 1] = fmaf(gw, ta1, g * r1);
    }

    #pragma unroll 8
    for (int h = 0; h < 32; h++) {
        const ulonglong2 wab = *reinterpret_cast<const ulonglong2*>(&swab[2 * h]);
        const ulonglong2 bw2 = *reinterpret_cast<const ulonglong2*>(&sbw2[2 * h]);
        #pragma unroll
        for (int pp = 0; pp < 8; pp++) {
            u64 z  = fma2(wab.x, X0p[pp], fma2(wab.y, X1p[pp], bw2.x));
            u64 za = z & 0x7FFFFFFF7FFFFFFFULL;      // |z| per half
            acc[pp] = fma2(bw2.y, add2(z, za), acc[pp]);  // += 0.5*w2*(z+|z|)
        }
    }

    #pragma unroll
    for (int pp = 0; pp < 8; pp++) {
        float a0, a1; unpack2(acc[pp], a0, a1);
        const float s0 = __fdividef(1.f, 1.f + __expf(-a0));
        const float s1 = __fdividef(1.f, 1.f + __expf(-a1));
        u[2 * pp]     = fmaf(ggi, s0, u[2 * pp]);
        u[2 * pp + 1] = fmaf(ggi, s1, u[2 * pp + 1]);
    }

    // replay coefficients
    const float aw = 0.5f * sp(paw[0]);
    const float ar = 0.5f * sp(par[0]);
    float ri[5], m[5], kta[5], ks[5];
    float Rsum = 0.f;
    #pragma unroll
    for (int i = 0; i < 5; i++) {
        const float r = sp(rcR[i]) * 0.1f;
        const float c = sp(rcC[i]) * 1e-5f;
        const float a = (i < 4) ? aw : ar;
        ri[i] = r; Rsum += r;
        const float cd = c * 900.f;
        kta[i] = cd * r;
        m[i]   = 1.f - 2.f * cd * r;
        ks[i]  = cd * a;
    }
    const float alpha = 1.f - g * (Rsum + win);

    float tm[5] = {0.f, 0.f, 0.f, 0.f, 0.f};
    float tz = 0.f;
    #pragma unroll
    for (int s = 0; s < 16; s++) {
        float tzc;
        if (WARM) tzc = __ldg(xb + 7 * s);   // exogenous gt carry
        else      tzc = tz;
        float S = tm[0] * ri[0];
        S = fmaf(tm[1], ri[1], S);
        S = fmaf(tm[2], ri[2], S);
        S = fmaf(tm[3], ri[3], S);
        S = fmaf(tm[4], ri[4], S);
        const float tznew = fmaf(alpha, tzc, fmaf(g, S, u[s]));
        g_tzz[(size_t)(t0 + s) * B_LEN + b] = tznew;
        const float tpz = ta[s] + tzc;
        #pragma unroll
        for (int i = 0; i < 5; i++)
            tm[i] = fmaf(kta[i], tpz, fmaf(ks[i], so[s], m[i] * tm[i]));
        tz = tznew;
    }
    if (!WARM) g_d[(size_t)(j * 6) * B_LEN + b] = tz;
    #pragma unroll
    for (int i = 0; i < 5; i++)
        g_d[(size_t)(j * 6 + 1 + i) * B_LEN + b] = tm[i];
}

// ---------------------------------------------------------------------------
// Scan over chunks: warm (diagonal) then full x <- A16 x + d.  2048 threads.
// ---------------------------------------------------------------------------
__global__ __launch_bounds__(256) void k_scan(const float* __restrict__ X)
{
    const int b = blockIdx.x * 256 + threadIdx.x;
    float A[36];
    #pragma unroll
    for (int i = 0; i < 36; i++) A[i] = g_A16[i];
    float m16[5], e15[5];
    #pragma unroll
    for (int i = 0; i < 5; i++) { m16[i] = g_m16[i]; e15[i] = g_e[15 * 5 + i]; }

    const float gt0 = X[(size_t)b * (T_LEN * 7)];
    const float ta0 = X[(size_t)b * (T_LEN * 7) + 1];
    float tm[5];
    #pragma unroll
    for (int i = 0; i < 5; i++) tm[i] = fmaf(0.7f, gt0, 0.3f * ta0);

    float h47 = 0.f;
    #pragma unroll
    for (int j = 0; j < WCH; j++) {
        #pragma unroll
        for (int i = 0; i < 5; i++) g_cs[(size_t)(j * 6 + 1 + i) * B_LEN + b] = tm[i];
        if (j == WCH - 1) {
            h47 = e15[0] * tm[0];
            #pragma unroll
            for (int i = 1; i < 5; i++) h47 = fmaf(e15[i], tm[i], h47);
        }
        #pragma unroll
        for (int i = 0; i < 5; i++)
            tm[i] = fmaf(m16[i], tm[i], g_d[(size_t)(j * 6 + 1 + i) * B_LEN + b]);
    }
    float x[6];
    x[0] = g_tzz[(size_t)47 * B_LEN + b] + h47;   // Tz carry entering t=48
    #pragma unroll
    for (int i = 0; i < 5; i++) x[1 + i] = tm[i];

    float dn[6];
    #pragma unroll
    for (int k = 0; k < 6; k++) dn[k] = g_d[(size_t)(WCH * 6 + k) * B_LEN + b];
    for (int j = WCH; j < N_CH; j++) {
        float d[6];
        #pragma unroll
        for (int k = 0; k < 6; k++) d[k] = dn[k];
        if (j + 1 < N_CH) {
            #pragma unroll
            for (int k = 0; k < 6; k++)
                dn[k] = g_d[(size_t)((j + 1) * 6 + k) * B_LEN + b];
        }
        #pragma unroll
        for (int k = 0; k < 6; k++) g_cs[(size_t)(j * 6 + k) * B_LEN + b] = x[k];
        float y[6];
        #pragma unroll
        for (int i = 0; i < 6; i++) {
            float a = d[i];
            #pragma unroll
            for (int k = 0; k < 6; k++) a = fmaf(A[i * 6 + k], x[k], a);
            y[i] = a;
        }
        #pragma unroll
        for (int k = 0; k < 6; k++) x[k] = y[k];
    }
}

// ---------------------------------------------------------------------------
// Emit: out[t] = tzz[t] + correction(chunk-start state). Fully parallel.
// ---------------------------------------------------------------------------
__global__ __launch_bounds__(256) void k_emit(float* __restrict__ out)
{
    __shared__ float sm[32][33];
    __shared__ float s_r0p[17 * 6];
    __shared__ float s_e[16 * 5];
    const int tid = threadIdx.x;
    if (tid < 102) s_r0p[tid] = g_r0p[tid];
    if (tid < 80)  s_e[tid]   = g_e[tid];
    __syncthreads();

    const int b0 = blockIdx.x * 32;
    const int t0 = blockIdx.y * 32;
    const int lane = tid & 31;
    const int row  = tid >> 5;           // 0..7; rows of 4 t's
    const int b = b0 + lane;
    const int tl0 = row * 4;
    const int jj = (t0 + tl0) >> 4;      // chunk, constant per thread
    const bool warm = (jj < WCH);

    float cs[6];
    #pragma unroll
    for (int k = 0; k < 6; k++) cs[k] = g_cs[(size_t)(jj * 6 + k) * B_LEN + b];

    #pragma unroll
    for (int pp = 0; pp < 4; pp++) {
        const int tl = tl0 + pp;
        const int t  = t0 + tl;
        const int s  = t & 15;
        float v = g_tzz[(size_t)t * B_LEN + b];
        if (warm) {
            #pragma unroll
            for (int i = 0; i < 5; i++) v = fmaf(s_e[s * 5 + i], cs[1 + i], v);
        } else {
            #pragma unroll
            for (int k = 0; k < 6; k++) v = fmaf(s_r0p[(s + 1) * 6 + k], cs[k], v);
        }
        sm[tl][lane] = v;
    }
    __syncthreads();
    #pragma unroll
    for (int pp = 0; pp < 4; pp++) {
        const int r = row * 4 + pp;
        out[(size_t)(b0 + r) * T_LEN + t0 + lane] = sm[lane][r];
    }
}

extern "C" void kernel_launch(void* const* d_in, const int* in_sizes, int n_in,
                              void* d_out, int out_size) {
    const float* X          = (const float*)d_in[0];
    const float* rcR        = (const float*)d_in[1];
    const float* rcC        = (const float*)d_in[2];
    const float* winR       = (const float*)d_in[3];
    const float* hvac_gain  = (const float*)d_in[4];
    const float* W1         = (const float*)d_in[5];
    const float* B1         = (const float*)d_in[6];
    const float* W2         = (const float*)d_in[7];
    const float* B2         = (const float*)d_in[8];
    const float* int_gain   = (const float*)d_in[9];
    const float* direct_gain= (const float*)d_in[10];
    const float* abs_wall   = (const float*)d_in[11];
    const float* abs_roof   = (const float*)d_in[12];
    const float* zone_C_inv = (const float*)d_in[13];
    float* out = (float*)d_out;

    k_setup<<<1, 32>>>(rcR, rcC, winR, abs_wall, abs_roof, zone_C_inv);
    dim3 gm(B_LEN / 128, N_CH - WCH);
    kA<false><<<gm, 128>>>(X, rcR, rcC, winR, W1, B1, W2, B2,
                           int_gain, hvac_gain, direct_gain,
                           abs_wall, abs_roof, zone_C_inv, WCH);
    dim3 gw(B_LEN / 128, WCH);
    kA<true><<<gw, 128>>>(X, rcR, rcC, winR, W1, B1, W2, B2,
                          int_gain, hvac_gain, direct_gain,
                          abs_wall, abs_roof, zone_C_inv, 0);
    k_scan<<<B_LEN / 256, 256>>>(X);
    dim3 ge(B_LEN / 32, T_LEN / 32);
    k_emit<<<ge, 256>>>(out);
}

// round 5
// speedup vs baseline: 1.6033x; 1.6033x over previous
#include <cuda_runtime.h>
#include <math.h>

#define T_LEN 1440
#define B_LEN 2048
#define N_RC  5
#define L_CH  16
#define N_CH  90      // 1440/16
#define WCH   3       // warm chunks (t < 48)

typedef unsigned long long u64;

__device__ float g_tzz[T_LEN * B_LEN];          // zero-state Tz trajectory
__device__ float g_d [(N_CH + 2) * 6 * B_LEN];  // per-chunk offsets (+pad)
__device__ float g_cs[N_CH * 6 * B_LEN];        // chunk-start states
__device__ float g_A16[36];                     // A^16 row-major
__device__ float g_r0p[17 * 6];                 // row0(A^n), n=1..16
__device__ float g_e[16 * 5];                   // g*ri_i*m_i^s
__device__ float g_m16[5];                      // m_i^16

__device__ __forceinline__ float sp(float x) {
    if (x > 20.f)  return x;
    if (x < -20.f) return expf(x);
    return log1pf(expf(x));
}

__device__ __forceinline__ u64 pack2(float lo, float hi) {
    u64 r; asm("mov.b64 %0,{%1,%2};" : "=l"(r) : "f"(lo), "f"(hi)); return r;
}
__device__ __forceinline__ void unpack2(u64 v, float& lo, float& hi) {
    asm("mov.b64 {%0,%1},%2;" : "=f"(lo), "=f"(hi) : "l"(v));
}
__device__ __forceinline__ u64 fma2(u64 a, u64 b, u64 c) {
    u64 d; asm("fma.rn.f32x2 %0,%1,%2,%3;" : "=l"(d) : "l"(a), "l"(b), "l"(c)); return d;
}
__device__ __forceinline__ u64 add2(u64 a, u64 b) {
    u64 d; asm("add.rn.f32x2 %0,%1,%2;" : "=l"(d) : "l"(a), "l"(b)); return d;
}

struct P { float ri[N_RC], m[N_RC], kta[N_RC], ks[N_RC], alpha, g, gw; };

__device__ __forceinline__ void loadP(P& p,
    const float* rcR, const float* rcC, const float* winR,
    const float* paw, const float* par, const float* pcz)
{
    const float aw = 0.5f * sp(paw[0]);
    const float ar = 0.5f * sp(par[0]);
    float Rsum = 0.f;
    #pragma unroll
    for (int i = 0; i < N_RC; i++) {
        const float r = sp(rcR[i]) * 0.1f;
        const float c = sp(rcC[i]) * 1e-5f;
        const float a = (i < 4) ? aw : ar;
        p.ri[i] = r; Rsum += r;
        const float cd = c * 900.f;
        p.kta[i] = cd * r;
        p.m[i]   = 1.f - 2.f * cd * r;
        p.ks[i]  = cd * a;
    }
    const float win = (sp(winR[0]) + sp(winR[1])) * 0.5f;
    const float cz  = sp(pcz[0]) * 1e-5f;
    p.g     = cz * 900.f;
    p.alpha = 1.f - p.g * (Rsum + win);
    p.gw    = p.g * win;
}

__device__ __forceinline__ void hstep(const P& p, float x[6]) {
    float tz = x[0];
    float S = x[1] * p.ri[0];
    S = fmaf(x[2], p.ri[1], S);
    S = fmaf(x[3], p.ri[2], S);
    S = fmaf(x[4], p.ri[3], S);
    S = fmaf(x[5], p.ri[4], S);
    const float tznew = fmaf(p.alpha, tz, p.g * S);
    #pragma unroll
    for (int i = 0; i < N_RC; i++)
        x[1 + i] = fmaf(p.kta[i], tz, p.m[i] * x[1 + i]);
    x[0] = tznew;
}

// ---------------------------------------------------------------------------
// Setup tables. 1 block of 32 threads.
// ---------------------------------------------------------------------------
__global__ void k_setup(
    const float* __restrict__ rcR, const float* __restrict__ rcC,
    const float* __restrict__ winR,
    const float* __restrict__ paw, const float* __restrict__ par,
    const float* __restrict__ pcz)
{
    const int j = threadIdx.x;
    P p; loadP(p, rcR, rcC, winR, paw, par, pcz);
    if (j < 6) {
        float x[6] = {0.f, 0.f, 0.f, 0.f, 0.f, 0.f};
        x[j] = 1.f;
        for (int n = 1; n <= L_CH; n++) {
            hstep(p, x);
            g_r0p[n * 6 + j] = x[0];
        }
        #pragma unroll
        for (int i = 0; i < 6; i++) g_A16[i * 6 + j] = x[i];
    } else if (j == 6) {
        float mp[N_RC];
        #pragma unroll
        for (int i = 0; i < N_RC; i++) mp[i] = 1.f;
        for (int s = 0; s < L_CH; s++) {
            #pragma unroll
            for (int i = 0; i < N_RC; i++) {
                g_e[s * 5 + i] = p.g * p.ri[i] * mp[i];
                mp[i] *= p.m[i];
            }
        }
        #pragma unroll
        for (int i = 0; i < N_RC; i++) g_m16[i] = mp[i];
    }
}

// ---------------------------------------------------------------------------
// Phase A (fused drives + zero-state replay). One thread = one (b, chunk).
// X tile staged coalesced through smem, transposed [col][row].
// ---------------------------------------------------------------------------
template<bool WARM>
__global__ __launch_bounds__(64) void kA(
    const float* __restrict__ X,
    const float* __restrict__ rcR, const float* __restrict__ rcC,
    const float* __restrict__ winR,
    const float* __restrict__ W1, const float* __restrict__ B1,
    const float* __restrict__ W2, const float* __restrict__ B2,
    const float* __restrict__ pig, const float* __restrict__ phg,
    const float* __restrict__ pdg,
    const float* __restrict__ paw, const float* __restrict__ par,
    const float* __restrict__ pcz, int jbase)
{
    __shared__ float s_in[112][65];          // [col 0..111][row 0..63]
    __shared__ __align__(16) u64 swab[64];   // [2h]=w1a dup, [2h+1]=w1b dup
    __shared__ __align__(16) u64 sbw2[64];   // [2h]=b1 dup,  [2h+1]=0.5*w2 dup
    const int tid = threadIdx.x;
    if (tid < 32) {
        const float wa = W1[2 * tid], wb = W1[2 * tid + 1];
        swab[2 * tid]     = pack2(wa, wa);
        swab[2 * tid + 1] = pack2(wb, wb);
        const float b1 = B1[tid], w2h = 0.5f * W2[tid];
        sbw2[2 * tid]     = pack2(b1, b1);
        sbw2[2 * tid + 1] = pack2(w2h, w2h);
    }

    const int j  = jbase + blockIdx.y;
    const int t0 = j * L_CH;
    const int b0 = blockIdx.x * 64;
    const int b  = b0 + tid;

    // stage 64 rows x 112 floats, coalesced
    const float* src = X + (size_t)b0 * (T_LEN * 7) + (size_t)t0 * 7;
    #pragma unroll
    for (int e = tid; e < 64 * 112; e += 64) {
        const int row = e / 112, c = e - row * 112;
        s_in[c][row] = src[(size_t)row * (T_LEN * 7) + c];
    }
    __syncthreads();

    const float gi  = 0.1f * sp(pig[0]);
    const float gh  = 0.1f * sp(phg[0]);
    const float gd  = 0.5f * sp(pdg[0]);
    const float g   = sp(pcz[0]) * 1e-5f * 900.f;
    const float win = (sp(winR[0]) + sp(winR[1])) * 0.5f;
    const float gw  = g * win;
    const float ggi = g * gi;
    const float b2v = B2[0];

    float u[16];
    u64 X0p[8], X1p[8], acc[8];
    const u64 b2_2 = pack2(b2v, b2v);

    #pragma unroll
    for (int pp = 0; pp < 8; pp++) {
        const int s0 = 2 * pp, s1 = 2 * pp + 1;
        const float ta0 = s_in[7 * s0 + 1][tid], so0 = s_in[7 * s0 + 2][tid];
        const float x00 = s_in[7 * s0 + 3][tid], x10 = s_in[7 * s0 + 4][tid];
        const float x20 = s_in[7 * s0 + 5][tid], hv0 = s_in[7 * s0 + 6][tid];
        const float ta1 = s_in[7 * s1 + 1][tid], so1 = s_in[7 * s1 + 2][tid];
        const float x01 = s_in[7 * s1 + 3][tid], x11 = s_in[7 * s1 + 4][tid];
        const float x21 = s_in[7 * s1 + 5][tid], hv1 = s_in[7 * s1 + 6][tid];
        X0p[pp] = pack2(x00, x01);
        X1p[pp] = pack2(x10, x11);
        acc[pp] = b2_2;
        u[s0] = fmaf(gw, ta0, g * fmaf(gd, so0, fmaf(gh, hv0, gi * x20)));
        u[s1] = fmaf(gw, ta1, g * fmaf(gd, so1, fmaf(gh, hv1, gi * x21)));
    }

    #pragma unroll 8
    for (int h = 0; h < 32; h++) {
        const ulonglong2 wab = *reinterpret_cast<const ulonglong2*>(&swab[2 * h]);
        const ulonglong2 bw2 = *reinterpret_cast<const ulonglong2*>(&sbw2[2 * h]);
        #pragma unroll
        for (int pp = 0; pp < 8; pp++) {
            u64 z  = fma2(wab.x, X0p[pp], fma2(wab.y, X1p[pp], bw2.x));
            u64 za = z & 0x7FFFFFFF7FFFFFFFULL;           // |z| per half
            acc[pp] = fma2(bw2.y, add2(z, za), acc[pp]);  // += 0.5*w2*(z+|z|)
        }
    }

    #pragma unroll
    for (int pp = 0; pp < 8; pp++) {
        float a0, a1; unpack2(acc[pp], a0, a1);
        const float sg0 = __fdividef(1.f, 1.f + __expf(-a0));
        const float sg1 = __fdividef(1.f, 1.f + __expf(-a1));
        u[2 * pp]     = fmaf(ggi, sg0, u[2 * pp]);
        u[2 * pp + 1] = fmaf(ggi, sg1, u[2 * pp + 1]);
    }

    // replay coefficients
    const float aw = 0.5f * sp(paw[0]);
    const float ar = 0.5f * sp(par[0]);
    float ri[5], m[5], kta[5], ks[5];
    float Rsum = 0.f;
    #pragma unroll
    for (int i = 0; i < 5; i++) {
        const float r = sp(rcR[i]) * 0.1f;
        const float c = sp(rcC[i]) * 1e-5f;
        const float a = (i < 4) ? aw : ar;
        ri[i] = r; Rsum += r;
        const float cd = c * 900.f;
        kta[i] = cd * r;
        m[i]   = 1.f - 2.f * cd * r;
        ks[i]  = cd * a;
    }
    const float alpha = 1.f - g * (Rsum + win);

    float tm[5] = {0.f, 0.f, 0.f, 0.f, 0.f};
    float tz = 0.f;
    #pragma unroll
    for (int s = 0; s < 16; s++) {
        const float tac = s_in[7 * s + 1][tid];
        const float soc = s_in[7 * s + 2][tid];
        float tzc;
        if (WARM) tzc = s_in[7 * s][tid];    // exogenous gt carry
        else      tzc = tz;
        float S = tm[0] * ri[0];
        S = fmaf(tm[1], ri[1], S);
        S = fmaf(tm[2], ri[2], S);
        S = fmaf(tm[3], ri[3], S);
        S = fmaf(tm[4], ri[4], S);
        const float tznew = fmaf(alpha, tzc, fmaf(g, S, u[s]));
        g_tzz[(size_t)(t0 + s) * B_LEN + b] = tznew;
        const float tpz = tac + tzc;
        #pragma unroll
        for (int i = 0; i < 5; i++)
            tm[i] = fmaf(kta[i], tpz, fmaf(ks[i], soc, m[i] * tm[i]));
        tz = tznew;
    }
    if (!WARM) g_d[(size_t)(j * 6) * B_LEN + b] = tz;
    #pragma unroll
    for (int i = 0; i < 5; i++)
        g_d[(size_t)(j * 6 + 1 + i) * B_LEN + b] = tm[i];
}

// ---------------------------------------------------------------------------
// Scan over chunks with batched double-buffered prefetch. 2048 threads.
// ---------------------------------------------------------------------------
__global__ __launch_bounds__(64) void k_scan(const float* __restrict__ X)
{
    const int b = blockIdx.x * 64 + threadIdx.x;

    // prefetch warm d's and initial values
    float wd[15];
    #pragma unroll
    for (int j = 0; j < WCH; j++)
        #pragma unroll
        for (int i = 0; i < 5; i++)
            wd[j * 5 + i] = g_d[(size_t)(j * 6 + 1 + i) * B_LEN + b];
    const float gt0   = X[(size_t)b * (T_LEN * 7)];
    const float ta0   = X[(size_t)b * (T_LEN * 7) + 1];
    const float tzz47 = g_tzz[(size_t)47 * B_LEN + b];

    // preload batch 0 (chunks 3..10)
    float buf[2][48];
    #pragma unroll
    for (int q = 0; q < 48; q++)
        buf[0][q] = g_d[(size_t)(WCH * 6 + q) * B_LEN + b];

    float A[36];
    #pragma unroll
    for (int i = 0; i < 36; i++) A[i] = g_A16[i];
    float m16[5], e15[5];
    #pragma unroll
    for (int i = 0; i < 5; i++) { m16[i] = g_m16[i]; e15[i] = g_e[15 * 5 + i]; }

    // warm chunks (diagonal Tmid dynamics)
    float tm[5];
    #pragma unroll
    for (int i = 0; i < 5; i++) tm[i] = fmaf(0.7f, gt0, 0.3f * ta0);
    float h47 = 0.f;
    #pragma unroll
    for (int j = 0; j < WCH; j++) {
        #pragma unroll
        for (int i = 0; i < 5; i++)
            g_cs[(size_t)(j * 6 + 1 + i) * B_LEN + b] = tm[i];
        if (j == WCH - 1) {
            h47 = e15[0] * tm[0];
            #pragma unroll
            for (int i = 1; i < 5; i++) h47 = fmaf(e15[i], tm[i], h47);
        }
        #pragma unroll
        for (int i = 0; i < 5; i++)
            tm[i] = fmaf(m16[i], tm[i], wd[j * 5 + i]);
    }
    float x[6];
    x[0] = tzz47 + h47;
    #pragma unroll
    for (int i = 0; i < 5; i++) x[1 + i] = tm[i];

    // 11 batches of 8 chunks (87 real chunks + 1 pad; pad never stored)
    #pragma unroll
    for (int batch = 0; batch < 11; batch++) {
        const int jb = WCH + batch * 8;
        const int cu = batch & 1;
        if (batch < 10) {
            #pragma unroll
            for (int q = 0; q < 48; q++)
                buf[cu ^ 1][q] = g_d[(size_t)((jb + 8) * 6 + q) * B_LEN + b];
        }
        const int nc = (batch < 10) ? 8 : 7;
        #pragma unroll
        for (int c = 0; c < 8; c++) {
            if (c >= nc) break;
            const int j = jb + c;
            #pragma unroll
            for (int k = 0; k < 6; k++)
                g_cs[(size_t)(j * 6 + k) * B_LEN + b] = x[k];
            float y[6];
            #pragma unroll
            for (int i = 0; i < 6; i++) {
                float a = buf[cu][c * 6 + i];
                #pragma unroll
                for (int k = 0; k < 6; k++) a = fmaf(A[i * 6 + k], x[k], a);
                y[i] = a;
            }
            #pragma unroll
            for (int k = 0; k < 6; k++) x[k] = y[k];
        }
    }
}

// ---------------------------------------------------------------------------
// Emit: out[t] = tzz[t] + correction(chunk-start state). Fully parallel.
// ---------------------------------------------------------------------------
__global__ __launch_bounds__(256) void k_emit(float* __restrict__ out)
{
    __shared__ float sm[32][33];
    __shared__ float s_r0p[17 * 6];
    __shared__ float s_e[16 * 5];
    const int tid = threadIdx.x;
    if (tid < 102) s_r0p[tid] = g_r0p[tid];
    if (tid < 80)  s_e[tid]   = g_e[tid];
    __syncthreads();

    const int b0 = blockIdx.x * 32;
    const int t0 = blockIdx.y * 32;
    const int lane = tid & 31;
    const int row  = tid >> 5;
    const int b = b0 + lane;
    const int tl0 = row * 4;
    const int jj = (t0 + tl0) >> 4;
    const bool warm = (jj < WCH);

    float cs[6];
    #pragma unroll
    for (int k = 0; k < 6; k++) cs[k] = g_cs[(size_t)(jj * 6 + k) * B_LEN + b];

    #pragma unroll
    for (int pp = 0; pp < 4; pp++) {
        const int tl = tl0 + pp;
        const int t  = t0 + tl;
        const int s  = t & 15;
        float v = g_tzz[(size_t)t * B_LEN + b];
        if (warm) {
            #pragma unroll
            for (int i = 0; i < 5; i++) v = fmaf(s_e[s * 5 + i], cs[1 + i], v);
        } else {
            #pragma unroll
            for (int k = 0; k < 6; k++) v = fmaf(s_r0p[(s + 1) * 6 + k], cs[k], v);
        }
        sm[tl][lane] = v;
    }
    __syncthreads();
    #pragma unroll
    for (int pp = 0; pp < 4; pp++) {
        const int r = row * 4 + pp;
        out[(size_t)(b0 + r) * T_LEN + t0 + lane] = sm[lane][r];
    }
}

extern "C" void kernel_launch(void* const* d_in, const int* in_sizes, int n_in,
                              void* d_out, int out_size) {
    const float* X          = (const float*)d_in[0];
    const float* rcR        = (const float*)d_in[1];
    const float* rcC        = (const float*)d_in[2];
    const float* winR       = (const float*)d_in[3];
    const float* hvac_gain  = (const float*)d_in[4];
    const float* W1         = (const float*)d_in[5];
    const float* B1         = (const float*)d_in[6];
    const float* W2         = (const float*)d_in[7];
    const float* B2         = (const float*)d_in[8];
    const float* int_gain   = (const float*)d_in[9];
    const float* direct_gain= (const float*)d_in[10];
    const float* abs_wall   = (const float*)d_in[11];
    const float* abs_roof   = (const float*)d_in[12];
    const float* zone_C_inv = (const float*)d_in[13];
    float* out = (float*)d_out;

    k_setup<<<1, 32>>>(rcR, rcC, winR, abs_wall, abs_roof, zone_C_inv);
    dim3 gm(B_LEN / 64, N_CH - WCH);
    kA<false><<<gm, 64>>>(X, rcR, rcC, winR, W1, B1, W2, B2,
                          int_gain, hvac_gain, direct_gain,
                          abs_wall, abs_roof, zone_C_inv, WCH);
    dim3 gw(B_LEN / 64, WCH);
    kA<true><<<gw, 64>>>(X, rcR, rcC, winR, W1, B1, W2, B2,
                         int_gain, hvac_gain, direct_gain,
                         abs_wall, abs_roof, zone_C_inv, 0);
    k_scan<<<B_LEN / 64, 64>>>(X);
    dim3 ge(B_LEN / 32, T_LEN / 32);
    k_emit<<<ge, 256>>>(out);
}

// round 6
// speedup vs baseline: 2.0095x; 1.2534x over previous
#include <cuda_runtime.h>
#include <math.h>

#define T_LEN 1440
#define B_LEN 2048
#define N_RC  5
#define L_CH  16
#define N_CH  90      // 1440/16
#define WCH   3       // warm chunks (t < 48)

typedef unsigned long long u64;

__device__ float g_tzz[T_LEN * B_LEN];          // zero-state Tz trajectory
__device__ float g_d [(N_CH + 2) * 6 * B_LEN];  // per-chunk offsets (+pad)
__device__ float g_cs[N_CH * 6 * B_LEN];        // chunk-start states

__device__ __forceinline__ float sp(float x) {
    if (x > 20.f)  return x;
    if (x < -20.f) return expf(x);
    return log1pf(expf(x));
}

__device__ __forceinline__ u64 pack2(float lo, float hi) {
    u64 r; asm("mov.b64 %0,{%1,%2};" : "=l"(r) : "f"(lo), "f"(hi)); return r;
}
__device__ __forceinline__ void unpack2(u64 v, float& lo, float& hi) {
    asm("mov.b64 {%0,%1},%2;" : "=f"(lo), "=f"(hi) : "l"(v));
}
__device__ __forceinline__ u64 fma2(u64 a, u64 b, u64 c) {
    u64 d; asm("fma.rn.f32x2 %0,%1,%2,%3;" : "=l"(d) : "l"(a), "l"(b), "l"(c)); return d;
}

struct P { float ri[N_RC], m[N_RC], kta[N_RC], ks[N_RC], alpha, g, gw; };

__device__ __forceinline__ void loadP(P& p,
    const float* rcR, const float* rcC, const float* winR,
    const float* paw, const float* par, const float* pcz)
{
    const float aw = 0.5f * sp(paw[0]);
    const float ar = 0.5f * sp(par[0]);
    float Rsum = 0.f;
    #pragma unroll
    for (int i = 0; i < N_RC; i++) {
        const float r = sp(rcR[i]) * 0.1f;
        const float c = sp(rcC[i]) * 1e-5f;
        const float a = (i < 4) ? aw : ar;
        p.ri[i] = r; Rsum += r;
        const float cd = c * 900.f;
        p.kta[i] = cd * r;
        p.m[i]   = 1.f - 2.f * cd * r;
        p.ks[i]  = cd * a;
    }
    const float win = (sp(winR[0]) + sp(winR[1])) * 0.5f;
    const float cz  = sp(pcz[0]) * 1e-5f;
    p.g     = cz * 900.f;
    p.alpha = 1.f - p.g * (Rsum + win);
    p.gw    = p.g * win;
}

__device__ __forceinline__ void hstep(const P& p, float x[6]) {
    float tz = x[0];
    float S = x[1] * p.ri[0];
    S = fmaf(x[2], p.ri[1], S);
    S = fmaf(x[3], p.ri[2], S);
    S = fmaf(x[4], p.ri[3], S);
    S = fmaf(x[5], p.ri[4], S);
    const float tznew = fmaf(p.alpha, tz, p.g * S);
    #pragma unroll
    for (int i = 0; i < N_RC; i++)
        x[1 + i] = fmaf(p.kta[i], tz, p.m[i] * x[1 + i]);
    x[0] = tznew;
}

// swizzled physical column for logical column L (compile-time at use sites)
#define SWC(L) ((((L) & ~3)) | (((((L) & 3)) + (((L) >> 5) & 3)) & 3))
#define SIN(L) s_in[SWC(L)][tid]

// ---------------------------------------------------------------------------
// Phase A (fused drives + zero-state replay). One thread = one (b, chunk).
// X tile staged via float4 loads into swizzled transposed smem.
// ---------------------------------------------------------------------------
__global__ __launch_bounds__(64) void kA(
    const float* __restrict__ X,
    const float* __restrict__ rcR, const float* __restrict__ rcC,
    const float* __restrict__ winR,
    const float* __restrict__ W1, const float* __restrict__ B1,
    const float* __restrict__ W2, const float* __restrict__ B2,
    const float* __restrict__ pig, const float* __restrict__ phg,
    const float* __restrict__ pdg,
    const float* __restrict__ paw, const float* __restrict__ par,
    const float* __restrict__ pcz)
{
    __shared__ float s_in[112][65];          // [physical col][row]
    __shared__ __align__(16) u64 swab[64];   // [2h]=w1a dup, [2h+1]=w1b dup
    __shared__ __align__(16) u64 sbw2[64];   // [2h]=b1 dup,  [2h+1]=0.5*w2 dup
    const int tid = threadIdx.x;
    if (tid < 32) {
        const float wa = W1[2 * tid], wb = W1[2 * tid + 1];
        swab[2 * tid]     = pack2(wa, wa);
        swab[2 * tid + 1] = pack2(wb, wb);
        const float b1 = B1[tid], w2h = 0.5f * W2[tid];
        sbw2[2 * tid]     = pack2(b1, b1);
        sbw2[2 * tid + 1] = pack2(w2h, w2h);
    }

    const int j  = blockIdx.y;
    const bool warm = (j < WCH);
    const int t0 = j * L_CH;
    const int b0 = blockIdx.x * 64;
    const int b  = b0 + tid;

    // stage 64 rows x 28 float4, coalesced; swizzled scatter to smem
    {
        const float4* src4 = reinterpret_cast<const float4*>(
            X + (size_t)b0 * (T_LEN * 7) + (size_t)t0 * 7);
        const int q  = tid & 31;
        const int rh = tid >> 5;
        if (q < 28) {
            const int qh = q >> 3;
            const int c0 = 4 * q + ((0 + qh) & 3);
            const int c1 = 4 * q + ((1 + qh) & 3);
            const int c2 = 4 * q + ((2 + qh) & 3);
            const int c3 = 4 * q + ((3 + qh) & 3);
            #pragma unroll
            for (int k = 0; k < 32; k++) {
                const int row = 2 * k + rh;
                const float4 v = src4[(size_t)row * ((T_LEN * 7) / 4) + q];
                s_in[c0][row] = v.x;
                s_in[c1][row] = v.y;
                s_in[c2][row] = v.z;
                s_in[c3][row] = v.w;
            }
        }
    }
    __syncthreads();

    const float gi  = 0.1f * sp(pig[0]);
    const float gh  = 0.1f * sp(phg[0]);
    const float gd  = 0.5f * sp(pdg[0]);
    const float g   = sp(pcz[0]) * 1e-5f * 900.f;
    const float win = (sp(winR[0]) + sp(winR[1])) * 0.5f;
    const float gw  = g * win;
    const float ggi = g * gi;
    const float b2v = B2[0];

    float u[16];
    u64 X0p[8], X1p[8], acc[8];
    const u64 b2_2 = pack2(b2v, b2v);

    #pragma unroll
    for (int pp = 0; pp < 8; pp++) {
        const int s0 = 2 * pp, s1 = 2 * pp + 1;
        const float ta0 = SIN(7 * s0 + 1), so0 = SIN(7 * s0 + 2);
        const float x00 = SIN(7 * s0 + 3), x10 = SIN(7 * s0 + 4);
        const float x20 = SIN(7 * s0 + 5), hv0 = SIN(7 * s0 + 6);
        const float ta1 = SIN(7 * s1 + 1), so1 = SIN(7 * s1 + 2);
        const float x01 = SIN(7 * s1 + 3), x11 = SIN(7 * s1 + 4);
        const float x21 = SIN(7 * s1 + 5), hv1 = SIN(7 * s1 + 6);
        X0p[pp] = pack2(x00, x01);
        X1p[pp] = pack2(x10, x11);
        acc[pp] = b2_2;
        u[s0] = fmaf(gw, ta0, g * fmaf(gd, so0, fmaf(gh, hv0, gi * x20)));
        u[s1] = fmaf(gw, ta1, g * fmaf(gd, so1, fmaf(gh, hv1, gi * x21)));
    }

    #pragma unroll 8
    for (int h = 0; h < 32; h++) {
        const ulonglong2 wab = *reinterpret_cast<const ulonglong2*>(&swab[2 * h]);
        const ulonglong2 bw2 = *reinterpret_cast<const ulonglong2*>(&sbw2[2 * h]);
        #pragma unroll
        for (int pp = 0; pp < 8; pp++) {
            u64 z  = fma2(wab.x, X0p[pp], fma2(wab.y, X1p[pp], bw2.x));
            u64 za = z & 0x7FFFFFFF7FFFFFFFULL;              // |z| per half
            acc[pp] = fma2(bw2.y, z, fma2(bw2.y, za, acc[pp]));
        }
    }

    #pragma unroll
    for (int pp = 0; pp < 8; pp++) {
        float a0, a1; unpack2(acc[pp], a0, a1);
        const float sg0 = __fdividef(1.f, 1.f + __expf(-a0));
        const float sg1 = __fdividef(1.f, 1.f + __expf(-a1));
        u[2 * pp]     = fmaf(ggi, sg0, u[2 * pp]);
        u[2 * pp + 1] = fmaf(ggi, sg1, u[2 * pp + 1]);
    }

    // replay coefficients
    const float aw = 0.5f * sp(paw[0]);
    const float ar = 0.5f * sp(par[0]);
    float ri[5], m[5], kta[5], ks[5];
    float Rsum = 0.f;
    #pragma unroll
    for (int i = 0; i < 5; i++) {
        const float r = sp(rcR[i]) * 0.1f;
        const float c = sp(rcC[i]) * 1e-5f;
        const float a = (i < 4) ? aw : ar;
        ri[i] = r; Rsum += r;
        const float cd = c * 900.f;
        kta[i] = cd * r;
        m[i]   = 1.f - 2.f * cd * r;
        ks[i]  = cd * a;
    }
    const float alpha = 1.f - g * (Rsum + win);

    float tm[5] = {0.f, 0.f, 0.f, 0.f, 0.f};
    float tz = 0.f;
    #pragma unroll
    for (int s = 0; s < 16; s++) {
        const float tac = SIN(7 * s + 1);
        const float soc = SIN(7 * s + 2);
        const float gtc = SIN(7 * s);
        const float tzc = warm ? gtc : tz;   // exogenous gt carry in warm region
        float S = tm[0] * ri[0];
        S = fmaf(tm[1], ri[1], S);
        S = fmaf(tm[2], ri[2], S);
        S = fmaf(tm[3], ri[3], S);
        S = fmaf(tm[4], ri[4], S);
        const float tznew = fmaf(alpha, tzc, fmaf(g, S, u[s]));
        g_tzz[(size_t)(t0 + s) * B_LEN + b] = tznew;
        const float tpz = tac + tzc;
        #pragma unroll
        for (int i = 0; i < 5; i++)
            tm[i] = fmaf(kta[i], tpz, fmaf(ks[i], soc, m[i] * tm[i]));
        tz = tznew;
    }
    if (!warm) g_d[(size_t)(j * 6) * B_LEN + b] = tz;
    #pragma unroll
    for (int i = 0; i < 5; i++)
        g_d[(size_t)(j * 6 + 1 + i) * B_LEN + b] = tm[i];
}

// ---------------------------------------------------------------------------
// Scan over chunks with batched double-buffered prefetch. 2048 threads.
// Tables computed block-locally.
// ---------------------------------------------------------------------------
__global__ __launch_bounds__(64) void k_scan(
    const float* __restrict__ X,
    const float* __restrict__ rcR, const float* __restrict__ rcC,
    const float* __restrict__ winR,
    const float* __restrict__ paw, const float* __restrict__ par,
    const float* __restrict__ pcz)
{
    __shared__ float sA[36];
    __shared__ float sm16[5], se15[5];
    const int tid = threadIdx.x;
    if (tid < 7) {
        P p; loadP(p, rcR, rcC, winR, paw, par, pcz);
        if (tid < 6) {
            float x[6] = {0.f, 0.f, 0.f, 0.f, 0.f, 0.f};
            x[tid] = 1.f;
            for (int n = 0; n < L_CH; n++) hstep(p, x);
            #pragma unroll
            for (int i = 0; i < 6; i++) sA[i * 6 + tid] = x[i];
        } else {
            float mp[5] = {1.f, 1.f, 1.f, 1.f, 1.f};
            for (int s = 0; s < L_CH; s++) {
                #pragma unroll
                for (int i = 0; i < 5; i++) {
                    if (s == 15) se15[i] = p.g * p.ri[i] * mp[i];
                    mp[i] *= p.m[i];
                }
            }
            #pragma unroll
            for (int i = 0; i < 5; i++) sm16[i] = mp[i];
        }
    }

    const int b = blockIdx.x * 64 + tid;

    // prefetch warm d's and initial values
    float wd[15];
    #pragma unroll
    for (int j = 0; j < WCH; j++)
        #pragma unroll
        for (int i = 0; i < 5; i++)
            wd[j * 5 + i] = g_d[(size_t)(j * 6 + 1 + i) * B_LEN + b];
    const float gt0   = X[(size_t)b * (T_LEN * 7)];
    const float ta0   = X[(size_t)b * (T_LEN * 7) + 1];
    const float tzz47 = g_tzz[(size_t)47 * B_LEN + b];

    // preload batch 0 (chunks 3..10)
    float buf[2][48];
    #pragma unroll
    for (int q = 0; q < 48; q++)
        buf[0][q] = g_d[(size_t)(WCH * 6 + q) * B_LEN + b];

    __syncthreads();
    float A[36];
    #pragma unroll
    for (int i = 0; i < 36; i++) A[i] = sA[i];
    float m16[5], e15[5];
    #pragma unroll
    for (int i = 0; i < 5; i++) { m16[i] = sm16[i]; e15[i] = se15[i]; }

    // warm chunks (diagonal Tmid dynamics)
    float tm[5];
    #pragma unroll
    for (int i = 0; i < 5; i++) tm[i] = fmaf(0.7f, gt0, 0.3f * ta0);
    float h47 = 0.f;
    #pragma unroll
    for (int j = 0; j < WCH; j++) {
        #pragma unroll
        for (int i = 0; i < 5; i++)
            g_cs[(size_t)(j * 6 + 1 + i) * B_LEN + b] = tm[i];
        if (j == WCH - 1) {
            h47 = e15[0] * tm[0];
            #pragma unroll
            for (int i = 1; i < 5; i++) h47 = fmaf(e15[i], tm[i], h47);
        }
        #pragma unroll
        for (int i = 0; i < 5; i++)
            tm[i] = fmaf(m16[i], tm[i], wd[j * 5 + i]);
    }
    float x[6];
    x[0] = tzz47 + h47;
    #pragma unroll
    for (int i = 0; i < 5; i++) x[1 + i] = tm[i];

    // 11 batches of 8 chunks (87 real chunks + 1 pad; pad never stored)
    #pragma unroll
    for (int batch = 0; batch < 11; batch++) {
        const int jb = WCH + batch * 8;
        const int cu = batch & 1;
        if (batch < 10) {
            #pragma unroll
            for (int q = 0; q < 48; q++)
                buf[cu ^ 1][q] = g_d[(size_t)((jb + 8) * 6 + q) * B_LEN + b];
        }
        const int nc = (batch < 10) ? 8 : 7;
        #pragma unroll
        for (int c = 0; c < 8; c++) {
            if (c >= nc) break;
            const int j = jb + c;
            #pragma unroll
            for (int k = 0; k < 6; k++)
                g_cs[(size_t)(j * 6 + k) * B_LEN + b] = x[k];
            float y[6];
            #pragma unroll
            for (int i = 0; i < 6; i++) {
                float a = buf[cu][c * 6 + i];
                #pragma unroll
                for (int k = 0; k < 6; k++) a = fmaf(A[i * 6 + k], x[k], a);
                y[i] = a;
            }
            #pragma unroll
            for (int k = 0; k < 6; k++) x[k] = y[k];
        }
    }
}

// ---------------------------------------------------------------------------
// Emit: out[t] = tzz[t] + correction(chunk-start state). Fully parallel.
// Tables computed block-locally.
// ---------------------------------------------------------------------------
__global__ __launch_bounds__(256) void k_emit(
    const float* __restrict__ rcR, const float* __restrict__ rcC,
    const float* __restrict__ winR,
    const float* __restrict__ paw, const float* __restrict__ par,
    const float* __restrict__ pcz,
    float* __restrict__ out)
{
    __shared__ float sm[32][33];
    __shared__ float s_r0p[17 * 6];
    __shared__ float s_e[16 * 5];
    const int tid = threadIdx.x;
    if (tid < 7) {
        P p; loadP(p, rcR, rcC, winR, paw, par, pcz);
        if (tid < 6) {
            float x[6] = {0.f, 0.f, 0.f, 0.f, 0.f, 0.f};
            x[tid] = 1.f;
            for (int n = 1; n <= L_CH; n++) {
                hstep(p, x);
                s_r0p[n * 6 + tid] = x[0];
            }
        } else {
            float mp[5] = {1.f, 1.f, 1.f, 1.f, 1.f};
            for (int s = 0; s < L_CH; s++) {
                #pragma unroll
                for (int i = 0; i < 5; i++) {
                    s_e[s * 5 + i] = p.g * p.ri[i] * mp[i];
                    mp[i] *= p.m[i];
                }
            }
        }
    }
    __syncthreads();

    const int b0 = blockIdx.x * 32;
    const int t0 = blockIdx.y * 32;
    const int lane = tid & 31;
    const int row  = tid >> 5;
    const int b = b0 + lane;
    const int tl0 = row * 4;
    const int jj = (t0 + tl0) >> 4;
    const bool warm = (jj < WCH);

    float cs[6];
    #pragma unroll
    for (int k = 0; k < 6; k++) cs[k] = g_cs[(size_t)(jj * 6 + k) * B_LEN + b];

    #pragma unroll
    for (int pp = 0; pp < 4; pp++) {
        const int tl = tl0 + pp;
        const int t  = t0 + tl;
        const int s  = t & 15;
        float v = g_tzz[(size_t)t * B_LEN + b];
        if (warm) {
            #pragma unroll
            for (int i = 0; i < 5; i++) v = fmaf(s_e[s * 5 + i], cs[1 + i], v);
        } else {
            #pragma unroll
            for (int k = 0; k < 6; k++) v = fmaf(s_r0p[(s + 1) * 6 + k], cs[k], v);
        }
        sm[tl][lane] = v;
    }
    __syncthreads();
    #pragma unroll
    for (int pp = 0; pp < 4; pp++) {
        const int r = row * 4 + pp;
        out[(size_t)(b0 + r) * T_LEN + t0 + lane] = sm[lane][r];
    }
}

extern "C" void kernel_launch(void* const* d_in, const int* in_sizes, int n_in,
                              void* d_out, int out_size) {
    const float* X          = (const float*)d_in[0];
    const float* rcR        = (const float*)d_in[1];
    const float* rcC        = (const float*)d_in[2];
    const float* winR       = (const float*)d_in[3];
    const float* hvac_gain  = (const float*)d_in[4];
    const float* W1         = (const float*)d_in[5];
    const float* B1         = (const float*)d_in[6];
    const float* W2         = (const float*)d_in[7];
    const float* B2         = (const float*)d_in[8];
    const float* int_gain   = (const float*)d_in[9];
    const float* direct_gain= (const float*)d_in[10];
    const float* abs_wall   = (const float*)d_in[11];
    const float* abs_roof   = (const float*)d_in[12];
    const float* zone_C_inv = (const float*)d_in[13];
    float* out = (float*)d_out;

    dim3 gA(B_LEN / 64, N_CH);
    kA<<<gA, 64>>>(X, rcR, rcC, winR, W1, B1, W2, B2,
                   int_gain, hvac_gain, direct_gain,
                   abs_wall, abs_roof, zone_C_inv);
    k_scan<<<B_LEN / 64, 64>>>(X, rcR, rcC, winR, abs_wall, abs_roof,
                               zone_C_inv);
    dim3 ge(B_LEN / 32, T_LEN / 32);
    k_emit<<<ge, 256>>>(rcR, rcC, winR, abs_wall, abs_roof, zone_C_inv, out);
}

// round 11
// speedup vs baseline: 2.9711x; 1.4785x over previous
#include <cuda_runtime.h>
#include <math.h>

#define T_LEN 1440
#define B_LEN 2048
#define N_RC  5
#define L_CH  16
#define N_CH  90      // 1440/16
#define WCH   3       // warm chunks (t < 48)

typedef unsigned long long u64;

__device__ float g_tzz[T_LEN * B_LEN];          // zero-state Tz trajectory
__device__ float g_d [(N_CH + 2) * 6 * B_LEN];  // per-chunk offsets (+pad)
__device__ float g_cs[N_CH * 6 * B_LEN];        // chunk-start states
__device__ float g_r0p[17 * 6];                 // row0(A^n), n=1..16 (from scan)
__device__ float g_e[16 * 5];                   // g*ri_i*m_i^s      (from scan)

__device__ __forceinline__ float sp(float x) {
    if (x > 20.f)  return x;
    if (x < -20.f) return expf(x);
    return log1pf(expf(x));
}

__device__ __forceinline__ u64 pack2(float lo, float hi) {
    u64 r; asm("mov.b64 %0,{%1,%2};" : "=l"(r) : "f"(lo), "f"(hi)); return r;
}
__device__ __forceinline__ void unpack2(u64 v, float& lo, float& hi) {
    asm("mov.b64 {%0,%1},%2;" : "=f"(lo), "=f"(hi) : "l"(v));
}
__device__ __forceinline__ u64 fma2(u64 a, u64 b, u64 c) {
    u64 d; asm("fma.rn.f32x2 %0,%1,%2,%3;" : "=l"(d) : "l"(a), "l"(b), "l"(c)); return d;
}

struct P { float ri[N_RC], m[N_RC], kta[N_RC], ks[N_RC], alpha, g, gw; };

__device__ __forceinline__ void loadP(P& p,
    const float* rcR, const float* rcC, const float* winR,
    const float* paw, const float* par, const float* pcz)
{
    const float aw = 0.5f * sp(paw[0]);
    const float ar = 0.5f * sp(par[0]);
    float Rsum = 0.f;
    #pragma unroll
    for (int i = 0; i < N_RC; i++) {
        const float r = sp(rcR[i]) * 0.1f;
        const float c = sp(rcC[i]) * 1e-5f;
        const float a = (i < 4) ? aw : ar;
        p.ri[i] = r; Rsum += r;
        const float cd = c * 900.f;
        p.kta[i] = cd * r;
        p.m[i]   = 1.f - 2.f * cd * r;
        p.ks[i]  = cd * a;
    }
    const float win = (sp(winR[0]) + sp(winR[1])) * 0.5f;
    const float cz  = sp(pcz[0]) * 1e-5f;
    p.g     = cz * 900.f;
    p.alpha = 1.f - p.g * (Rsum + win);
    p.gw    = p.g * win;
}

__device__ __forceinline__ void hstep(const P& p, float x[6]) {
    float tz = x[0];
    float S = x[1] * p.ri[0];
    S = fmaf(x[2], p.ri[1], S);
    S = fmaf(x[3], p.ri[2], S);
    S = fmaf(x[4], p.ri[3], S);
    S = fmaf(x[5], p.ri[4], S);
    const float tznew = fmaf(p.alpha, tz, p.g * S);
    #pragma unroll
    for (int i = 0; i < N_RC; i++)
        x[1 + i] = fmaf(p.kta[i], tz, p.m[i] * x[1 + i]);
    x[0] = tznew;
}

// swizzled physical column for logical column L (compile-time at use sites)
#define SWC(L) ((((L) & ~3)) | (((((L) & 3)) + (((L) >> 5) & 3)) & 3))
#define SIN(L) s_in[SWC(L)][tid]

// ---------------------------------------------------------------------------
// Phase A (fused drives + zero-state replay). One thread = one (b, chunk).
// ---------------------------------------------------------------------------
__global__ __launch_bounds__(64) void kA(
    const float* __restrict__ X,
    const float* __restrict__ rcR, const float* __restrict__ rcC,
    const float* __restrict__ winR,
    const float* __restrict__ W1, const float* __restrict__ B1,
    const float* __restrict__ W2, const float* __restrict__ B2,
    const float* __restrict__ pig, const float* __restrict__ phg,
    const float* __restrict__ pdg,
    const float* __restrict__ paw, const float* __restrict__ par,
    const float* __restrict__ pcz)
{
    __shared__ float s_in[112][65];          // [physical col][row]
    __shared__ __align__(16) u64 swab[64];   // [2h]=w1a dup, [2h+1]=w1b dup
    __shared__ __align__(16) u64 sbw2[64];   // [2h]=b1 dup,  [2h+1]=0.5*w2 dup
    const int tid = threadIdx.x;
    if (tid < 32) {
        const float wa = W1[2 * tid], wb = W1[2 * tid + 1];
        swab[2 * tid]     = pack2(wa, wa);
        swab[2 * tid + 1] = pack2(wb, wb);
        const float b1 = B1[tid], w2h = 0.5f * W2[tid];
        sbw2[2 * tid]     = pack2(b1, b1);
        sbw2[2 * tid + 1] = pack2(w2h, w2h);
    }

    const int j  = blockIdx.y;
    const bool warm = (j < WCH);
    const int t0 = j * L_CH;
    const int b0 = blockIdx.x * 64;
    const int b  = b0 + tid;

    // stage 64 rows x 28 float4: base pointers + immediate offsets only.
    // tile start (b0+row, t0, 0) = (b0+row)*2520 + j*28 in float4 units.
    {
        const int q  = tid & 31;
        const int rh = tid >> 5;
        if (q < 28) {
            const float4* src = reinterpret_cast<const float4*>(X)
                + (size_t)b0 * 2520 + (size_t)rh * 2520 + (size_t)j * 28 + q;
            const int qh = q >> 3;
            float* d0 = &s_in[4 * q + ((0 + qh) & 3)][rh];
            float* d1 = &s_in[4 * q + ((1 + qh) & 3)][rh];
            float* d2 = &s_in[4 * q + ((2 + qh) & 3)][rh];
            float* d3 = &s_in[4 * q + ((3 + qh) & 3)][rh];
            #pragma unroll
            for (int k = 0; k < 32; k++) {
                const float4 v = src[(size_t)k * 5040];  // 2 rows per k
                d0[2 * k] = v.x;
                d1[2 * k] = v.y;
                d2[2 * k] = v.z;
                d3[2 * k] = v.w;
            }
        }
    }
    __syncthreads();

    const float gi  = 0.1f * sp(pig[0]);
    const float gh  = 0.1f * sp(phg[0]);
    const float gd  = 0.5f * sp(pdg[0]);
    const float g   = sp(pcz[0]) * 1e-5f * 900.f;
    const float win = (sp(winR[0]) + sp(winR[1])) * 0.5f;
    const float gw  = g * win;
    const float ggi = g * gi;
    const float b2v = B2[0];
    const u64 b2_2  = pack2(b2v, b2v);

    float u[16];
    // MLP in two halves of 4 pp (8 timesteps) to bound register pressure
    #pragma unroll
    for (int half = 0; half < 2; half++) {
        u64 X0p[4], X1p[4], acc[4];
        #pragma unroll
        for (int pp = 0; pp < 4; pp++) {
            const int s0 = 8 * half + 2 * pp, s1 = s0 + 1;
            const float ta0 = SIN(7 * s0 + 1), so0 = SIN(7 * s0 + 2);
            const float x00 = SIN(7 * s0 + 3), x10 = SIN(7 * s0 + 4);
            const float x20 = SIN(7 * s0 + 5), hv0 = SIN(7 * s0 + 6);
            const float ta1 = SIN(7 * s1 + 1), so1 = SIN(7 * s1 + 2);
            const float x01 = SIN(7 * s1 + 3), x11 = SIN(7 * s1 + 4);
            const float x21 = SIN(7 * s1 + 5), hv1 = SIN(7 * s1 + 6);
            X0p[pp] = pack2(x00, x01);
            X1p[pp] = pack2(x10, x11);
            acc[pp] = b2_2;
            u[s0] = fmaf(gw, ta0, g * fmaf(gd, so0, fmaf(gh, hv0, gi * x20)));
            u[s1] = fmaf(gw, ta1, g * fmaf(gd, so1, fmaf(gh, hv1, gi * x21)));
        }
        #pragma unroll 8
        for (int h = 0; h < 32; h++) {
            const ulonglong2 wab = *reinterpret_cast<const ulonglong2*>(&swab[2 * h]);
            const ulonglong2 bw2 = *reinterpret_cast<const ulonglong2*>(&sbw2[2 * h]);
            #pragma unroll
            for (int pp = 0; pp < 4; pp++) {
                u64 z  = fma2(wab.x, X0p[pp], fma2(wab.y, X1p[pp], bw2.x));
                u64 za = z & 0x7FFFFFFF7FFFFFFFULL;              // |z| per half
                acc[pp] = fma2(bw2.y, z, fma2(bw2.y, za, acc[pp]));
            }
        }
        #pragma unroll
        for (int pp = 0; pp < 4; pp++) {
            float a0, a1; unpack2(acc[pp], a0, a1);
            const float sg0 = __fdividef(1.f, 1.f + __expf(-a0));
            const float sg1 = __fdividef(1.f, 1.f + __expf(-a1));
            const int s0 = 8 * half + 2 * pp;
            u[s0]     = fmaf(ggi, sg0, u[s0]);
            u[s0 + 1] = fmaf(ggi, sg1, u[s0 + 1]);
        }
    }

    // replay coefficients
    const float aw = 0.5f * sp(paw[0]);
    const float ar = 0.5f * sp(par[0]);
    float ri[5], m[5], kta[5], ks[5];
    float Rsum = 0.f;
    #pragma unroll
    for (int i = 0; i < 5; i++) {
        const float r = sp(rcR[i]) * 0.1f;
        const float c = sp(rcC[i]) * 1e-5f;
        const float a = (i < 4) ? aw : ar;
        ri[i] = r; Rsum += r;
        const float cd = c * 900.f;
        kta[i] = cd * r;
        m[i]   = 1.f - 2.f * cd * r;
        ks[i]  = cd * a;
    }
    const float alpha = 1.f - g * (Rsum + win);

    float* pz = g_tzz + (unsigned)(t0 * B_LEN + b);   // + s*2048 (imm)
    float tm[5] = {0.f, 0.f, 0.f, 0.f, 0.f};
    float tz = 0.f;
    #pragma unroll
    for (int s = 0; s < 16; s++) {
        const float tac = SIN(7 * s + 1);
        const float soc = SIN(7 * s + 2);
        float tzc;
        if (warm) tzc = SIN(7 * s);          // exogenous gt carry
        else      tzc = tz;
        float S = tm[0] * ri[0];
        S = fmaf(tm[1], ri[1], S);
        S = fmaf(tm[2], ri[2], S);
        S = fmaf(tm[3], ri[3], S);
        S = fmaf(tm[4], ri[4], S);
        const float tznew = fmaf(alpha, tzc, fmaf(g, S, u[s]));
        pz[s * B_LEN] = tznew;
        const float tpz = tac + tzc;
        #pragma unroll
        for (int i = 0; i < 5; i++)
            tm[i] = fmaf(kta[i], tpz, fmaf(ks[i], soc, m[i] * tm[i]));
        tz = tznew;
    }
    float* pd = g_d + (unsigned)(j * 6 * B_LEN + b);  // + i*2048 (imm)
    if (!warm) pd[0] = tz;
    #pragma unroll
    for (int i = 0; i < 5; i++) pd[(1 + i) * B_LEN] = tm[i];
}

// ---------------------------------------------------------------------------
// Scan over chunks, 4-chunk double-buffered prefetch. Also emits the A-power
// tables to global (block 0) for k_emit.
// ---------------------------------------------------------------------------
__global__ __launch_bounds__(64) void k_scan(
    const float* __restrict__ X,
    const float* __restrict__ rcR, const float* __restrict__ rcC,
    const float* __restrict__ winR,
    const float* __restrict__ paw, const float* __restrict__ par,
    const float* __restrict__ pcz)
{
    __shared__ float sA[36];
    __shared__ float sm16[5], se15[5];
    const int tid = threadIdx.x;
    if (tid < 7) {
        P p; loadP(p, rcR, rcC, winR, paw, par, pcz);
        if (tid < 6) {
            float x[6] = {0.f, 0.f, 0.f, 0.f, 0.f, 0.f};
            x[tid] = 1.f;
            for (int n = 1; n <= L_CH; n++) {
                hstep(p, x);
                if (blockIdx.x == 0) g_r0p[n * 6 + tid] = x[0];
            }
            #pragma unroll
            for (int i = 0; i < 6; i++) sA[i * 6 + tid] = x[i];
        } else {
            float mp[5] = {1.f, 1.f, 1.f, 1.f, 1.f};
            for (int s = 0; s < L_CH; s++) {
                #pragma unroll
                for (int i = 0; i < 5; i++) {
                    const float e = p.g * p.ri[i] * mp[i];
                    if (blockIdx.x == 0) g_e[s * 5 + i] = e;
                    if (s == 15) se15[i] = e;
                    mp[i] *= p.m[i];
                }
            }
            #pragma unroll
            for (int i = 0; i < 5; i++) sm16[i] = mp[i];
        }
    }

    const int b = blockIdx.x * 64 + tid;

    // prefetch warm d's and initial values
    const float* pdw = g_d + (unsigned)b;
    float wd[15];
    #pragma unroll
    for (int j = 0; j < WCH; j++)
        #pragma unroll
        for (int i = 0; i < 5; i++)
            wd[j * 5 + i] = pdw[(j * 6 + 1 + i) * B_LEN];
    const float gt0   = X[(size_t)b * (T_LEN * 7)];
    const float ta0   = X[(size_t)b * (T_LEN * 7) + 1];
    const float tzz47 = g_tzz[(unsigned)(47 * B_LEN + b)];

    // preload batch 0 (chunks 3..6)
    float buf[2][24];
    const float* pd = g_d + (unsigned)(WCH * 6 * B_LEN + b);
    #pragma unroll
    for (int q = 0; q < 24; q++) buf[0][q] = pd[q * B_LEN];

    __syncthreads();
    float A[36];
    #pragma unroll
    for (int i = 0; i < 36; i++) A[i] = sA[i];
    float m16[5], e15[5];
    #pragma unroll
    for (int i = 0; i < 5; i++) { m16[i] = sm16[i]; e15[i] = se15[i]; }

    // warm chunks (diagonal Tmid dynamics)
    float* pcs = g_cs + (unsigned)b;
    float tm[5];
    #pragma unroll
    for (int i = 0; i < 5; i++) tm[i] = fmaf(0.7f, gt0, 0.3f * ta0);
    float h47 = 0.f;
    #pragma unroll
    for (int j = 0; j < WCH; j++) {
        #pragma unroll
        for (int i = 0; i < 5; i++)
            pcs[(j * 6 + 1 + i) * B_LEN] = tm[i];
        if (j == WCH - 1) {
            h47 = e15[0] * tm[0];
            #pragma unroll
            for (int i = 1; i < 5; i++) h47 = fmaf(e15[i], tm[i], h47);
        }
        #pragma unroll
        for (int i = 0; i < 5; i++)
            tm[i] = fmaf(m16[i], tm[i], wd[j * 5 + i]);
    }
    float x[6];
    x[0] = tzz47 + h47;
    #pragma unroll
    for (int i = 0; i < 5; i++) x[1 + i] = tm[i];

    // 22 batches of 4 chunks (87 real + 1 pad; pad computed but never stored)
    pcs = g_cs + (unsigned)(WCH * 6 * B_LEN + b);
    #pragma unroll
    for (int batch = 0; batch < 22; batch++) {
        const int cu = batch & 1;
        if (batch < 21) {
            const float* pn = pd + (unsigned)(24 * B_LEN);
            #pragma unroll
            for (int q = 0; q < 24; q++) buf[cu ^ 1][q] = pn[q * B_LEN];
        }
        const int nc = (batch < 21) ? 4 : 3;
        #pragma unroll
        for (int c = 0; c < 4; c++) {
            const bool live = (c < nc);
            if (live) {
                #pragma unroll
                for (int k = 0; k < 6; k++) pcs[(c * 6 + k) * B_LEN] = x[k];
            }
            float y[6];
            #pragma unroll
            for (int i = 0; i < 6; i++) {
                float a = buf[cu][c * 6 + i];
                #pragma unroll
                for (int k = 0; k < 6; k++) a = fmaf(A[i * 6 + k], x[k], a);
                y[i] = a;
            }
            if (live) {
                #pragma unroll
                for (int k = 0; k < 6; k++) x[k] = y[k];
            }
        }
        pd  += (unsigned)(24 * B_LEN);
        pcs += (unsigned)(24 * B_LEN);
    }
}

// ---------------------------------------------------------------------------
// Emit: out[t] = tzz[t] + correction(chunk-start state). Fully parallel.
// Tables loaded from global (written by k_scan block 0).
// ---------------------------------------------------------------------------
__global__ __launch_bounds__(256) void k_emit(float* __restrict__ out)
{
    __shared__ float sm[32][33];
    __shared__ float s_r0p[17 * 6];
    __shared__ float s_e[16 * 5];
    const int tid = threadIdx.x;
    if (tid < 102) s_r0p[tid] = g_r0p[tid];
    if (tid < 80)  s_e[tid]   = g_e[tid];
    __syncthreads();

    const int b0 = blockIdx.x * 32;
    const int t0 = blockIdx.y * 32;
    const int lane = tid & 31;
    const int row  = tid >> 5;
    const int b = b0 + lane;
    const int tl0 = row * 4;
    const int jj = (t0 + tl0) >> 4;
    const bool warm = (jj < WCH);

    const float* pcs = g_cs + (unsigned)(jj * 6 * B_LEN + b);
    float cs[6];
    #pragma unroll
    for (int k = 0; k < 6; k++) cs[k] = pcs[k * B_LEN];

    const float* ptz = g_tzz + (unsigned)((t0 + tl0) * B_LEN + b);
    #pragma unroll
    for (int pp = 0; pp < 4; pp++) {
        const int s = (t0 + tl0 + pp) & 15;
        float v = ptz[pp * B_LEN];
        if (warm) {
            #pragma unroll
            for (int i = 0; i < 5; i++) v = fmaf(s_e[s * 5 + i], cs[1 + i], v);
        } else {
            #pragma unroll
            for (int k = 0; k < 6; k++) v = fmaf(s_r0p[(s + 1) * 6 + k], cs[k], v);
        }
        sm[tl0 + pp][lane] = v;
    }
    __syncthreads();
    #pragma unroll
    for (int pp = 0; pp < 4; pp++) {
        const int r = tl0 + pp;
        out[(unsigned)((b0 + r) * T_LEN + t0 + lane)] = sm[lane][r];
    }
}

extern "C" void kernel_launch(void* const* d_in, const int* in_sizes, int n_in,
                              void* d_out, int out_size) {
    const float* X          = (const float*)d_in[0];
    const float* rcR        = (const float*)d_in[1];
    const float* rcC        = (const float*)d_in[2];
    const float* winR       = (const float*)d_in[3];
    const float* hvac_gain  = (const float*)d_in[4];
    const float* W1         = (const float*)d_in[5];
    const float* B1         = (const float*)d_in[6];
    const float* W2         = (const float*)d_in[7];
    const float* B2         = (const float*)d_in[8];
    const float* int_gain   = (const float*)d_in[9];
    const float* direct_gain= (const float*)d_in[10];
    const float* abs_wall   = (const float*)d_in[11];
    const float* abs_roof   = (const float*)d_in[12];
    const float* zone_C_inv = (const float*)d_in[13];
    float* out = (float*)d_out;

    dim3 gA(B_LEN / 64, N_CH);
    kA<<<gA, 64>>>(X, rcR, rcC, winR, W1, B1, W2, B2,
                   int_gain, hvac_gain, direct_gain,
                   abs_wall, abs_roof, zone_C_inv);
    k_scan<<<B_LEN / 64, 64>>>(X, rcR, rcC, winR, abs_wall, abs_roof,
                               zone_C_inv);
    dim3 ge(B_LEN / 32, T_LEN / 32);
    k_emit<<<ge, 256>>>(out);
}

// round 12
// speedup vs baseline: 3.2689x; 1.1002x over previous
#include <cuda_runtime.h>
#include <math.h>

#define T_LEN 1440
#define B_LEN 2048
#define N_RC  5
#define L_CH  16
#define N_CH  90      // 1440/16
#define WCH   3       // warm chunks (t < 48)

typedef unsigned long long u64;

__device__ float g_tzz[T_LEN * B_LEN];          // zero-state Tz trajectory
__device__ float g_d [(N_CH + 2) * 6 * B_LEN];  // per-chunk offsets (+pad)
__device__ float g_cs[N_CH * 6 * B_LEN];        // chunk-start states
__device__ float g_r0p[17 * 6];                 // row0(A^n), n=1..16 (from scan)
__device__ float g_e[16 * 5];                   // g*ri_i*m_i^s      (from scan)

__device__ __forceinline__ float sp(float x) {
    if (x > 20.f)  return x;
    if (x < -20.f) return expf(x);
    return log1pf(expf(x));
}

__device__ __forceinline__ u64 pack2(float lo, float hi) {
    u64 r; asm("mov.b64 %0,{%1,%2};" : "=l"(r) : "f"(lo), "f"(hi)); return r;
}
__device__ __forceinline__ void unpack2(u64 v, float& lo, float& hi) {
    asm("mov.b64 {%0,%1},%2;" : "=f"(lo), "=f"(hi) : "l"(v));
}
__device__ __forceinline__ u64 fma2(u64 a, u64 b, u64 c) {
    u64 d; asm("fma.rn.f32x2 %0,%1,%2,%3;" : "=l"(d) : "l"(a), "l"(b), "l"(c)); return d;
}

struct P { float ri[N_RC], m[N_RC], kta[N_RC], ks[N_RC], alpha, g, gw; };

__device__ __forceinline__ void loadP(P& p,
    const float* rcR, const float* rcC, const float* winR,
    const float* paw, const float* par, const float* pcz)
{
    const float aw = 0.5f * sp(paw[0]);
    const float ar = 0.5f * sp(par[0]);
    float Rsum = 0.f;
    #pragma unroll
    for (int i = 0; i < N_RC; i++) {
        const float r = sp(rcR[i]) * 0.1f;
        const float c = sp(rcC[i]) * 1e-5f;
        const float a = (i < 4) ? aw : ar;
        p.ri[i] = r; Rsum += r;
        const float cd = c * 900.f;
        p.kta[i] = cd * r;
        p.m[i]   = 1.f - 2.f * cd * r;
        p.ks[i]  = cd * a;
    }
    const float win = (sp(winR[0]) + sp(winR[1])) * 0.5f;
    const float cz  = sp(pcz[0]) * 1e-5f;
    p.g     = cz * 900.f;
    p.alpha = 1.f - p.g * (Rsum + win);
    p.gw    = p.g * win;
}

__device__ __forceinline__ void hstep(const P& p, float x[6]) {
    float tz = x[0];
    float S = x[1] * p.ri[0];
    S = fmaf(x[2], p.ri[1], S);
    S = fmaf(x[3], p.ri[2], S);
    S = fmaf(x[4], p.ri[3], S);
    S = fmaf(x[5], p.ri[4], S);
    const float tznew = fmaf(p.alpha, tz, p.g * S);
    #pragma unroll
    for (int i = 0; i < N_RC; i++)
        x[1 + i] = fmaf(p.kta[i], tz, p.m[i] * x[1 + i]);
    x[0] = tznew;
}

// swizzled physical column for logical column L (compile-time at use sites)
#define SWC(L) ((((L) & ~3)) | (((((L) & 3)) + (((L) >> 5) & 3)) & 3))
#define SINR(L, R) s_in[SWC(L)][R]

// ---------------------------------------------------------------------------
// Phase A (fused drives + zero-state replay).
// 256 threads: staging (8 rows/thread) -> MLP (4 timesteps/thread, all
// threads) -> replay (threads 0..63, one chain per batch row).
// ---------------------------------------------------------------------------
__global__ __launch_bounds__(256) void kA(
    const float* __restrict__ X,
    const float* __restrict__ rcR, const float* __restrict__ rcC,
    const float* __restrict__ winR,
    const float* __restrict__ W1, const float* __restrict__ B1,
    const float* __restrict__ W2, const float* __restrict__ B2,
    const float* __restrict__ pig, const float* __restrict__ phg,
    const float* __restrict__ pdg,
    const float* __restrict__ paw, const float* __restrict__ par,
    const float* __restrict__ pcz)
{
    __shared__ float s_in[112][65];          // [physical col][row]
    __shared__ float u_s[64][17];            // per-(row,step) drive term
    __shared__ __align__(16) u64 swab[64];   // [2h]=w1a dup, [2h+1]=w1b dup
    __shared__ __align__(16) u64 sbw2[64];   // [2h]=b1 dup,  [2h+1]=0.5*w2 dup
    const int tid = threadIdx.x;
    if (tid < 32) {
        const float wa = W1[2 * tid], wb = W1[2 * tid + 1];
        swab[2 * tid]     = pack2(wa, wa);
        swab[2 * tid + 1] = pack2(wb, wb);
        const float b1 = B1[tid], w2h = 0.5f * W2[tid];
        sbw2[2 * tid]     = pack2(b1, b1);
        sbw2[2 * tid + 1] = pack2(w2h, w2h);
    }

    const int j  = blockIdx.y;
    const bool warm = (j < WCH);
    const int t0 = j * L_CH;
    const int b0 = blockIdx.x * 64;

    // stage 64 rows x 28 float4: 256 threads, 8 rows each, coalesced.
    // tile start (b0+row, t0, 0) = (b0+row)*2520 + j*28 in float4 units.
    {
        const int q  = tid & 31;
        const int rh = tid >> 5;             // 0..7
        if (q < 28) {
            const float4* src = reinterpret_cast<const float4*>(X)
                + (size_t)b0 * 2520 + (size_t)rh * 2520 + (size_t)j * 28 + q;
            const int qh = q >> 3;
            float* d0 = &s_in[4 * q + ((0 + qh) & 3)][rh];
            float* d1 = &s_in[4 * q + ((1 + qh) & 3)][rh];
            float* d2 = &s_in[4 * q + ((2 + qh) & 3)][rh];
            float* d3 = &s_in[4 * q + ((3 + qh) & 3)][rh];
            #pragma unroll
            for (int k = 0; k < 8; k++) {
                const float4 v = src[(size_t)k * 8 * 2520];  // rows rh+8k
                d0[8 * k] = v.x;
                d1[8 * k] = v.y;
                d2[8 * k] = v.z;
                d3[8 * k] = v.w;
            }
        }
    }
    __syncthreads();

    const float gi  = 0.1f * sp(pig[0]);
    const float gh  = 0.1f * sp(phg[0]);
    const float gd  = 0.5f * sp(pdg[0]);
    const float g   = sp(pcz[0]) * 1e-5f * 900.f;
    const float win = (sp(winR[0]) + sp(winR[1])) * 0.5f;
    const float gw  = g * win;
    const float ggi = g * gi;
    const float b2v = B2[0];
    const u64 b2_2  = pack2(b2v, b2v);

    // MLP phase: thread -> (row = tid&63, timesteps 4*pg .. 4*pg+3)
    {
        const int row = tid & 63;
        const int pg  = tid >> 6;            // 0..3
        u64 X0p[2], X1p[2], acc[2];
        float uu[4];
        #pragma unroll
        for (int pp = 0; pp < 2; pp++) {
            const int s0 = 4 * pg + 2 * pp, s1 = s0 + 1;
            const float ta0 = SINR(7 * s0 + 1, row), so0 = SINR(7 * s0 + 2, row);
            const float x00 = SINR(7 * s0 + 3, row), x10 = SINR(7 * s0 + 4, row);
            const float x20 = SINR(7 * s0 + 5, row), hv0 = SINR(7 * s0 + 6, row);
            const float ta1 = SINR(7 * s1 + 1, row), so1 = SINR(7 * s1 + 2, row);
            const float x01 = SINR(7 * s1 + 3, row), x11 = SINR(7 * s1 + 4, row);
            const float x21 = SINR(7 * s1 + 5, row), hv1 = SINR(7 * s1 + 6, row);
            X0p[pp] = pack2(x00, x01);
            X1p[pp] = pack2(x10, x11);
            acc[pp] = b2_2;
            uu[2 * pp]     = fmaf(gw, ta0, g * fmaf(gd, so0, fmaf(gh, hv0, gi * x20)));
            uu[2 * pp + 1] = fmaf(gw, ta1, g * fmaf(gd, so1, fmaf(gh, hv1, gi * x21)));
        }
        #pragma unroll 8
        for (int h = 0; h < 32; h++) {
            const ulonglong2 wab = *reinterpret_cast<const ulonglong2*>(&swab[2 * h]);
            const ulonglong2 bw2 = *reinterpret_cast<const ulonglong2*>(&sbw2[2 * h]);
            #pragma unroll
            for (int pp = 0; pp < 2; pp++) {
                u64 z  = fma2(wab.x, X0p[pp], fma2(wab.y, X1p[pp], bw2.x));
                u64 za = z & 0x7FFFFFFF7FFFFFFFULL;              // |z| per half
                acc[pp] = fma2(bw2.y, z, fma2(bw2.y, za, acc[pp]));
            }
        }
        #pragma unroll
        for (int pp = 0; pp < 2; pp++) {
            float a0, a1; unpack2(acc[pp], a0, a1);
            const float sg0 = __fdividef(1.f, 1.f + __expf(-a0));
            const float sg1 = __fdividef(1.f, 1.f + __expf(-a1));
            uu[2 * pp]     = fmaf(ggi, sg0, uu[2 * pp]);
            uu[2 * pp + 1] = fmaf(ggi, sg1, uu[2 * pp + 1]);
        }
        #pragma unroll
        for (int k = 0; k < 4; k++) u_s[row][4 * pg + k] = uu[k];
    }
    __syncthreads();

    // Replay phase: threads 0..63, one sequential chain per batch row.
    if (tid < 64) {
        const float aw = 0.5f * sp(paw[0]);
        const float ar = 0.5f * sp(par[0]);
        float ri[5], m[5], kta[5], ks[5];
        float Rsum = 0.f;
        #pragma unroll
        for (int i = 0; i < 5; i++) {
            const float r = sp(rcR[i]) * 0.1f;
            const float c = sp(rcC[i]) * 1e-5f;
            const float a = (i < 4) ? aw : ar;
            ri[i] = r; Rsum += r;
            const float cd = c * 900.f;
            kta[i] = cd * r;
            m[i]   = 1.f - 2.f * cd * r;
            ks[i]  = cd * a;
        }
        const float alpha = 1.f - g * (Rsum + win);

        const int b = b0 + tid;
        float* pz = g_tzz + (unsigned)(t0 * B_LEN + b);   // + s*2048 (imm)
        float tm[5] = {0.f, 0.f, 0.f, 0.f, 0.f};
        float tz = 0.f;
        #pragma unroll
        for (int s = 0; s < 16; s++) {
            const float tac = SINR(7 * s + 1, tid);
            const float soc = SINR(7 * s + 2, tid);
            const float us  = u_s[tid][s];
            float tzc;
            if (warm) tzc = SINR(7 * s, tid);    // exogenous gt carry
            else      tzc = tz;
            float S = tm[0] * ri[0];
            S = fmaf(tm[1], ri[1], S);
            S = fmaf(tm[2], ri[2], S);
            S = fmaf(tm[3], ri[3], S);
            S = fmaf(tm[4], ri[4], S);
            const float tznew = fmaf(alpha, tzc, fmaf(g, S, us));
            pz[s * B_LEN] = tznew;
            const float tpz = tac + tzc;
            #pragma unroll
            for (int i = 0; i < 5; i++)
                tm[i] = fmaf(kta[i], tpz, fmaf(ks[i], soc, m[i] * tm[i]));
            tz = tznew;
        }
        float* pd = g_d + (unsigned)(j * 6 * B_LEN + b);  // + i*2048 (imm)
        if (!warm) pd[0] = tz;
        #pragma unroll
        for (int i = 0; i < 5; i++) pd[(1 + i) * B_LEN] = tm[i];
    }
}

// ---------------------------------------------------------------------------
// Scan over chunks, 4-chunk double-buffered prefetch. Also emits the A-power
// tables to global (block 0) for k_emit.
// ---------------------------------------------------------------------------
__global__ __launch_bounds__(64) void k_scan(
    const float* __restrict__ X,
    const float* __restrict__ rcR, const float* __restrict__ rcC,
    const float* __restrict__ winR,
    const float* __restrict__ paw, const float* __restrict__ par,
    const float* __restrict__ pcz)
{
    __shared__ float sA[36];
    __shared__ float sm16[5], se15[5];
    const int tid = threadIdx.x;
    if (tid < 7) {
        P p; loadP(p, rcR, rcC, winR, paw, par, pcz);
        if (tid < 6) {
            float x[6] = {0.f, 0.f, 0.f, 0.f, 0.f, 0.f};
            x[tid] = 1.f;
            for (int n = 1; n <= L_CH; n++) {
                hstep(p, x);
                if (blockIdx.x == 0) g_r0p[n * 6 + tid] = x[0];
            }
            #pragma unroll
            for (int i = 0; i < 6; i++) sA[i * 6 + tid] = x[i];
        } else {
            float mp[5] = {1.f, 1.f, 1.f, 1.f, 1.f};
            for (int s = 0; s < L_CH; s++) {
                #pragma unroll
                for (int i = 0; i < 5; i++) {
                    const float e = p.g * p.ri[i] * mp[i];
                    if (blockIdx.x == 0) g_e[s * 5 + i] = e;
                    if (s == 15) se15[i] = e;
                    mp[i] *= p.m[i];
                }
            }
            #pragma unroll
            for (int i = 0; i < 5; i++) sm16[i] = mp[i];
        }
    }

    const int b = blockIdx.x * 64 + tid;

    // prefetch warm d's and initial values
    const float* pdw = g_d + (unsigned)b;
    float wd[15];
    #pragma unroll
    for (int j = 0; j < WCH; j++)
        #pragma unroll
        for (int i = 0; i < 5; i++)
            wd[j * 5 + i] = pdw[(j * 6 + 1 + i) * B_LEN];
    const float gt0   = X[(size_t)b * (T_LEN * 7)];
    const float ta0   = X[(size_t)b * (T_LEN * 7) + 1];
    const float tzz47 = g_tzz[(unsigned)(47 * B_LEN + b)];

    // preload batch 0 (chunks 3..6)
    float buf[2][24];
    const float* pd = g_d + (unsigned)(WCH * 6 * B_LEN + b);
    #pragma unroll
    for (int q = 0; q < 24; q++) buf[0][q] = pd[q * B_LEN];

    __syncthreads();
    float A[36];
    #pragma unroll
    for (int i = 0; i < 36; i++) A[i] = sA[i];
    float m16[5], e15[5];
    #pragma unroll
    for (int i = 0; i < 5; i++) { m16[i] = sm16[i]; e15[i] = se15[i]; }

    // warm chunks (diagonal Tmid dynamics)
    float* pcs = g_cs + (unsigned)b;
    float tm[5];
    #pragma unroll
    for (int i = 0; i < 5; i++) tm[i] = fmaf(0.7f, gt0, 0.3f * ta0);
    float h47 = 0.f;
    #pragma unroll
    for (int j = 0; j < WCH; j++) {
        #pragma unroll
        for (int i = 0; i < 5; i++)
            pcs[(j * 6 + 1 + i) * B_LEN] = tm[i];
        if (j == WCH - 1) {
            h47 = e15[0] * tm[0];
            #pragma unroll
            for (int i = 1; i < 5; i++) h47 = fmaf(e15[i], tm[i], h47);
        }
        #pragma unroll
        for (int i = 0; i < 5; i++)
            tm[i] = fmaf(m16[i], tm[i], wd[j * 5 + i]);
    }
    float x[6];
    x[0] = tzz47 + h47;
    #pragma unroll
    for (int i = 0; i < 5; i++) x[1 + i] = tm[i];

    // 22 batches of 4 chunks (87 real + 1 pad; pad computed but never stored)
    pcs = g_cs + (unsigned)(WCH * 6 * B_LEN + b);
    #pragma unroll
    for (int batch = 0; batch < 22; batch++) {
        const int cu = batch & 1;
        if (batch < 21) {
            const float* pn = pd + (unsigned)(24 * B_LEN);
            #pragma unroll
            for (int q = 0; q < 24; q++) buf[cu ^ 1][q] = pn[q * B_LEN];
        }
        const int nc = (batch < 21) ? 4 : 3;
        #pragma unroll
        for (int c = 0; c < 4; c++) {
            const bool live = (c < nc);
            if (live) {
                #pragma unroll
                for (int k = 0; k < 6; k++) pcs[(c * 6 + k) * B_LEN] = x[k];
            }
            float y[6];
            #pragma unroll
            for (int i = 0; i < 6; i++) {
                float a = buf[cu][c * 6 + i];
                #pragma unroll
                for (int k = 0; k < 6; k++) a = fmaf(A[i * 6 + k], x[k], a);
                y[i] = a;
            }
            if (live) {
                #pragma unroll
                for (int k = 0; k < 6; k++) x[k] = y[k];
            }
        }
        pd  += (unsigned)(24 * B_LEN);
        pcs += (unsigned)(24 * B_LEN);
    }
}

// ---------------------------------------------------------------------------
// Emit: out[t] = tzz[t] + correction(chunk-start state). Fully parallel.
// Tables loaded from global (written by k_scan block 0).
// ---------------------------------------------------------------------------
__global__ __launch_bounds__(256) void k_emit(float* __restrict__ out)
{
    __shared__ float sm[32][33];
    __shared__ float s_r0p[17 * 6];
    __shared__ float s_e[16 * 5];
    const int tid = threadIdx.x;
    if (tid < 102) s_r0p[tid] = g_r0p[tid];
    if (tid < 80)  s_e[tid]   = g_e[tid];
    __syncthreads();

    const int b0 = blockIdx.x * 32;
    const int t0 = blockIdx.y * 32;
    const int lane = tid & 31;
    const int row  = tid >> 5;
    const int b = b0 + lane;
    const int tl0 = row * 4;
    const int jj = (t0 + tl0) >> 4;
    const bool warm = (jj < WCH);

    const float* pcs = g_cs + (unsigned)(jj * 6 * B_LEN + b);
    float cs[6];
    #pragma unroll
    for (int k = 0; k < 6; k++) cs[k] = pcs[k * B_LEN];

    const float* ptz = g_tzz + (unsigned)((t0 + tl0) * B_LEN + b);
    #pragma unroll
    for (int pp = 0; pp < 4; pp++) {
        const int s = (t0 + tl0 + pp) & 15;
        float v = ptz[pp * B_LEN];
        if (warm) {
            #pragma unroll
            for (int i = 0; i < 5; i++) v = fmaf(s_e[s * 5 + i], cs[1 + i], v);
        } else {
            #pragma unroll
            for (int k = 0; k < 6; k++) v = fmaf(s_r0p[(s + 1) * 6 + k], cs[k], v);
        }
        sm[tl0 + pp][lane] = v;
    }
    __syncthreads();
    #pragma unroll
    for (int pp = 0; pp < 4; pp++) {
        const int r = tl0 + pp;
        out[(unsigned)((b0 + r) * T_LEN + t0 + lane)] = sm[lane][r];
    }
}

extern "C" void kernel_launch(void* const* d_in, const int* in_sizes, int n_in,
                              void* d_out, int out_size) {
    const float* X          = (const float*)d_in[0];
    const float* rcR        = (const float*)d_in[1];
    const float* rcC        = (const float*)d_in[2];
    const float* winR       = (const float*)d_in[3];
    const float* hvac_gain  = (const float*)d_in[4];
    const float* W1         = (const float*)d_in[5];
    const float* B1         = (const float*)d_in[6];
    const float* W2         = (const float*)d_in[7];
    const float* B2         = (const float*)d_in[8];
    const float* int_gain   = (const float*)d_in[9];
    const float* direct_gain= (const float*)d_in[10];
    const float* abs_wall   = (const float*)d_in[11];
    const float* abs_roof   = (const float*)d_in[12];
    const float* zone_C_inv = (const float*)d_in[13];
    float* out = (float*)d_out;

    dim3 gA(B_LEN / 64, N_CH);
    kA<<<gA, 256>>>(X, rcR, rcC, winR, W1, B1, W2, B2,
                    int_gain, hvac_gain, direct_gain,
                    abs_wall, abs_roof, zone_C_inv);
    k_scan<<<B_LEN / 64, 64>>>(X, rcR, rcC, winR, abs_wall, abs_roof,
                               zone_C_inv);
    dim3 ge(B_LEN / 32, T_LEN / 32);
    k_emit<<<ge, 256>>>(out);
}

// round 13
// speedup vs baseline: 3.3699x; 1.0309x over previous
#include <cuda_runtime.h>
#include <math.h>

#define T_LEN 1440
#define B_LEN 2048
#define N_RC  5
#define L_CH  16
#define N_CH  90      // 1440/16
#define WCH   3       // warm chunks (t < 48)

typedef unsigned long long u64;

__device__ float g_tzz[T_LEN * B_LEN];          // zero-state Tz trajectory
__device__ float g_d [(N_CH + 2) * 6 * B_LEN];  // per-chunk offsets (+pad)
__device__ float g_cs[N_CH * 6 * B_LEN];        // chunk-start states
__device__ float g_r0p[17 * 6];                 // row0(A^n), n=1..16 (from scan)
__device__ float g_e[16 * 5];                   // g*ri_i*m_i^s      (from scan)
__device__ u64   g_swab[64];                    // [2h]=w1a dup, [2h+1]=w1b dup
__device__ u64   g_sbw2[64];                    // [2h]=b1 dup,  [2h+1]=0.5*w2 dup
__device__ u64   g_cdup[3];                     // C0,C1,CB duplicated pairs
__device__ float g_c[27];                       // scalars + replay arrays

__device__ __forceinline__ float sp(float x) {
    if (x > 20.f)  return x;
    if (x < -20.f) return expf(x);
    return log1pf(expf(x));
}

__device__ __forceinline__ u64 pack2(float lo, float hi) {
    u64 r; asm("mov.b64 %0,{%1,%2};" : "=l"(r) : "f"(lo), "f"(hi)); return r;
}
__device__ __forceinline__ void unpack2(u64 v, float& lo, float& hi) {
    asm("mov.b64 {%0,%1},%2;" : "=f"(lo), "=f"(hi) : "l"(v));
}
__device__ __forceinline__ u64 fma2(u64 a, u64 b, u64 c) {
    u64 d; asm("fma.rn.f32x2 %0,%1,%2,%3;" : "=l"(d) : "l"(a), "l"(b), "l"(c)); return d;
}

struct P { float ri[N_RC], m[N_RC], kta[N_RC], ks[N_RC], alpha, g, gw; };

__device__ __forceinline__ void loadP(P& p,
    const float* rcR, const float* rcC, const float* winR,
    const float* paw, const float* par, const float* pcz)
{
    const float aw = 0.5f * sp(paw[0]);
    const float ar = 0.5f * sp(par[0]);
    float Rsum = 0.f;
    #pragma unroll
    for (int i = 0; i < N_RC; i++) {
        const float r = sp(rcR[i]) * 0.1f;
        const float c = sp(rcC[i]) * 1e-5f;
        const float a = (i < 4) ? aw : ar;
        p.ri[i] = r; Rsum += r;
        const float cd = c * 900.f;
        p.kta[i] = cd * r;
        p.m[i]   = 1.f - 2.f * cd * r;
        p.ks[i]  = cd * a;
    }
    const float win = (sp(winR[0]) + sp(winR[1])) * 0.5f;
    const float cz  = sp(pcz[0]) * 1e-5f;
    p.g     = cz * 900.f;
    p.alpha = 1.f - p.g * (Rsum + win);
    p.gw    = p.g * win;
}

__device__ __forceinline__ void hstep(const P& p, float x[6]) {
    float tz = x[0];
    float S = x[1] * p.ri[0];
    S = fmaf(x[2], p.ri[1], S);
    S = fmaf(x[3], p.ri[2], S);
    S = fmaf(x[4], p.ri[3], S);
    S = fmaf(x[5], p.ri[4], S);
    const float tznew = fmaf(p.alpha, tz, p.g * S);
    #pragma unroll
    for (int i = 0; i < N_RC; i++)
        x[1 + i] = fmaf(p.kta[i], tz, p.m[i] * x[1 + i]);
    x[0] = tznew;
}

// ---------------------------------------------------------------------------
// Precompute all scalar constants + packed weight tables. 1 block, 32 thr.
// ---------------------------------------------------------------------------
__global__ void k_pre(
    const float* __restrict__ rcR, const float* __restrict__ rcC,
    const float* __restrict__ winR,
    const float* __restrict__ W1, const float* __restrict__ B1,
    const float* __restrict__ W2, const float* __restrict__ B2,
    const float* __restrict__ pig, const float* __restrict__ phg,
    const float* __restrict__ pdg,
    const float* __restrict__ paw, const float* __restrict__ par,
    const float* __restrict__ pcz)
{
    const int tid = threadIdx.x;
    // packed duplicated weight tables
    {
        const float wa = W1[2 * tid], wb = W1[2 * tid + 1];
        g_swab[2 * tid]     = pack2(wa, wa);
        g_swab[2 * tid + 1] = pack2(wb, wb);
        const float b1 = B1[tid], w2h = 0.5f * W2[tid];
        g_sbw2[2 * tid]     = pack2(b1, b1);
        g_sbw2[2 * tid + 1] = pack2(w2h, w2h);
    }
    if (tid == 0) {
        const float gi  = 0.1f * sp(pig[0]);
        const float gh  = 0.1f * sp(phg[0]);
        const float gd  = 0.5f * sp(pdg[0]);
        const float g   = sp(pcz[0]) * 1e-5f * 900.f;
        const float win = (sp(winR[0]) + sp(winR[1])) * 0.5f;
        const float aw  = 0.5f * sp(paw[0]);
        const float ar  = 0.5f * sp(par[0]);
        float Rsum = 0.f;
        #pragma unroll
        for (int i = 0; i < 5; i++) {
            const float r = sp(rcR[i]) * 0.1f;
            const float c = sp(rcC[i]) * 1e-5f;
            const float a = (i < 4) ? aw : ar;
            Rsum += r;
            const float cd = c * 900.f;
            g_c[7 + i]  = r;                   // ri
            g_c[12 + i] = 1.f - 2.f * cd * r;  // m
            g_c[17 + i] = cd * r;              // kta
            g_c[22 + i] = cd * a;              // ks
        }
        g_c[0] = g * win;      // gw
        g_c[1] = g * gd;       // gds
        g_c[2] = g * gh;       // ghs
        g_c[3] = g * gi;       // gis (also ggi)
        g_c[4] = g * gi;       // ggi
        g_c[5] = 1.f - g * (Rsum + win);  // alpha
        g_c[6] = g;
        // folded linear MLP part
        float C0 = 0.f, C1 = 0.f, CB = B2[0];
        for (int h = 0; h < 32; h++) {
            const float w2h = 0.5f * W2[h];
            C0 = fmaf(w2h, W1[2 * h], C0);
            C1 = fmaf(w2h, W1[2 * h + 1], C1);
            CB = fmaf(w2h, B1[h], CB);
        }
        g_cdup[0] = pack2(C0, C0);
        g_cdup[1] = pack2(C1, C1);
        g_cdup[2] = pack2(CB, CB);
    }
}

// swizzled physical column for logical column L (compile-time at use sites)
#define SWC(L) ((((L) & ~3)) | (((((L) & 3)) + (((L) >> 5) & 3)) & 3))
#define SINR(L, R) s_in[SWC(L)][R]

// ---------------------------------------------------------------------------
// Phase A (fused drives + zero-state replay).
// 256 threads: staging (8 rows/thread) -> MLP (4 timesteps/thread, all
// threads) -> replay (threads 0..63, one chain per batch row).
// ---------------------------------------------------------------------------
__global__ __launch_bounds__(256) void kA(const float* __restrict__ X)
{
    __shared__ float s_in[112][65];          // [physical col][row]
    __shared__ float u_s[64][17];            // per-(row,step) drive term
    __shared__ __align__(16) u64 swab[64];
    __shared__ __align__(16) u64 sbw2[64];
    __shared__ float s_c[5];
    __shared__ u64 s_cd[3];
    const int tid = threadIdx.x;
    if (tid < 64) { swab[tid] = g_swab[tid]; sbw2[tid] = g_sbw2[tid]; }
    else if (tid < 69)  s_c[tid - 64]  = g_c[tid - 64];
    else if (tid < 72)  s_cd[tid - 69] = g_cdup[tid - 69];

    const int j  = blockIdx.y;
    const bool warm = (j < WCH);
    const int t0 = j * L_CH;
    const int b0 = blockIdx.x * 64;

    // stage 64 rows x 28 float4: 256 threads, 8 rows each, coalesced.
    {
        const int q  = tid & 31;
        const int rh = tid >> 5;             // 0..7
        if (q < 28) {
            const float4* src = reinterpret_cast<const float4*>(X)
                + (size_t)b0 * 2520 + (size_t)rh * 2520 + (size_t)j * 28 + q;
            const int qh = q >> 3;
            float* d0 = &s_in[4 * q + ((0 + qh) & 3)][rh];
            float* d1 = &s_in[4 * q + ((1 + qh) & 3)][rh];
            float* d2 = &s_in[4 * q + ((2 + qh) & 3)][rh];
            float* d3 = &s_in[4 * q + ((3 + qh) & 3)][rh];
            #pragma unroll
            for (int k = 0; k < 8; k++) {
                const float4 v = src[(size_t)k * 8 * 2520];  // rows rh+8k
                d0[8 * k] = v.x;
                d1[8 * k] = v.y;
                d2[8 * k] = v.z;
                d3[8 * k] = v.w;
            }
        }
    }
    __syncthreads();

    // MLP phase: thread -> (row = tid&63, timesteps 4*pg .. 4*pg+3)
    {
        const float gw  = s_c[0];
        const float gds = s_c[1];
        const float ghs = s_c[2];
        const float gis = s_c[3];
        const float ggi = s_c[4];
        const u64 c0d = s_cd[0], c1d = s_cd[1], cbd = s_cd[2];

        const int row = tid & 63;
        const int pg  = tid >> 6;            // 0..3
        u64 X0p[2], X1p[2], acc[2];
        float uu[4];
        #pragma unroll
        for (int pp = 0; pp < 2; pp++) {
            const int s0 = 4 * pg + 2 * pp, s1 = s0 + 1;
            const float ta0 = SINR(7 * s0 + 1, row), so0 = SINR(7 * s0 + 2, row);
            const float x00 = SINR(7 * s0 + 3, row), x10 = SINR(7 * s0 + 4, row);
            const float x20 = SINR(7 * s0 + 5, row), hv0 = SINR(7 * s0 + 6, row);
            const float ta1 = SINR(7 * s1 + 1, row), so1 = SINR(7 * s1 + 2, row);
            const float x01 = SINR(7 * s1 + 3, row), x11 = SINR(7 * s1 + 4, row);
            const float x21 = SINR(7 * s1 + 5, row), hv1 = SINR(7 * s1 + 6, row);
            X0p[pp] = pack2(x00, x01);
            X1p[pp] = pack2(x10, x11);
            acc[pp] = fma2(c0d, X0p[pp], fma2(c1d, X1p[pp], cbd));
            uu[2 * pp]     = fmaf(gw, ta0, fmaf(gds, so0, fmaf(ghs, hv0, gis * x20)));
            uu[2 * pp + 1] = fmaf(gw, ta1, fmaf(gds, so1, fmaf(ghs, hv1, gis * x21)));
        }
        #pragma unroll 8
        for (int h = 0; h < 32; h++) {
            const ulonglong2 wab = *reinterpret_cast<const ulonglong2*>(&swab[2 * h]);
            const ulonglong2 bw2 = *reinterpret_cast<const ulonglong2*>(&sbw2[2 * h]);
            #pragma unroll
            for (int pp = 0; pp < 2; pp++) {
                u64 z  = fma2(wab.x, X0p[pp], fma2(wab.y, X1p[pp], bw2.x));
                u64 za = z & 0x7FFFFFFF7FFFFFFFULL;      // |z| per half
                acc[pp] = fma2(bw2.y, za, acc[pp]);      // += 0.5*w2*|z|
            }
        }
        #pragma unroll
        for (int pp = 0; pp < 2; pp++) {
            float a0, a1; unpack2(acc[pp], a0, a1);
            const float sg0 = __fdividef(1.f, 1.f + __expf(-a0));
            const float sg1 = __fdividef(1.f, 1.f + __expf(-a1));
            uu[2 * pp]     = fmaf(ggi, sg0, uu[2 * pp]);
            uu[2 * pp + 1] = fmaf(ggi, sg1, uu[2 * pp + 1]);
        }
        #pragma unroll
        for (int k = 0; k < 4; k++) u_s[row][4 * pg + k] = uu[k];
    }
    __syncthreads();

    // Replay phase: threads 0..63, one sequential chain per batch row.
    if (tid < 64) {
        const float alpha = g_c[5];
        const float g     = g_c[6];
        float ri[5], m[5], kta[5], ks[5];
        #pragma unroll
        for (int i = 0; i < 5; i++) {
            ri[i]  = g_c[7 + i];
            m[i]   = g_c[12 + i];
            kta[i] = g_c[17 + i];
            ks[i]  = g_c[22 + i];
        }

        const int b = b0 + tid;
        float* pz = g_tzz + (unsigned)(t0 * B_LEN + b);   // + s*2048 (imm)
        float tm[5] = {0.f, 0.f, 0.f, 0.f, 0.f};
        float tz = 0.f;
        #pragma unroll
        for (int s = 0; s < 16; s++) {
            const float tac = SINR(7 * s + 1, tid);
            const float soc = SINR(7 * s + 2, tid);
            const float us  = u_s[tid][s];
            float tzc;
            if (warm) tzc = SINR(7 * s, tid);    // exogenous gt carry
            else      tzc = tz;
            float S = tm[0] * ri[0];
            S = fmaf(tm[1], ri[1], S);
            S = fmaf(tm[2], ri[2], S);
            S = fmaf(tm[3], ri[3], S);
            S = fmaf(tm[4], ri[4], S);
            const float tznew = fmaf(alpha, tzc, fmaf(g, S, us));
            pz[s * B_LEN] = tznew;
            const float tpz = tac + tzc;
            #pragma unroll
            for (int i = 0; i < 5; i++)
                tm[i] = fmaf(kta[i], tpz, fmaf(ks[i], soc, m[i] * tm[i]));
            tz = tznew;
        }
        float* pd = g_d + (unsigned)(j * 6 * B_LEN + b);  // + i*2048 (imm)
        if (!warm) pd[0] = tz;
        #pragma unroll
        for (int i = 0; i < 5; i++) pd[(1 + i) * B_LEN] = tm[i];
    }
}

// ---------------------------------------------------------------------------
// Scan over chunks, 4-chunk double-buffered prefetch. Also emits the A-power
// tables to global (block 0) for k_emit.
// ---------------------------------------------------------------------------
__global__ __launch_bounds__(64) void k_scan(
    const float* __restrict__ X,
    const float* __restrict__ rcR, const float* __restrict__ rcC,
    const float* __restrict__ winR,
    const float* __restrict__ paw, const float* __restrict__ par,
    const float* __restrict__ pcz)
{
    __shared__ float sA[36];
    __shared__ float sm16[5], se15[5];
    const int tid = threadIdx.x;
    if (tid < 7) {
        P p; loadP(p, rcR, rcC, winR, paw, par, pcz);
        if (tid < 6) {
            float x[6] = {0.f, 0.f, 0.f, 0.f, 0.f, 0.f};
            x[tid] = 1.f;
            for (int n = 1; n <= L_CH; n++) {
                hstep(p, x);
                if (blockIdx.x == 0) g_r0p[n * 6 + tid] = x[0];
            }
            #pragma unroll
            for (int i = 0; i < 6; i++) sA[i * 6 + tid] = x[i];
        } else {
            float mp[5] = {1.f, 1.f, 1.f, 1.f, 1.f};
            for (int s = 0; s < L_CH; s++) {
                #pragma unroll
                for (int i = 0; i < 5; i++) {
                    const float e = p.g * p.ri[i] * mp[i];
                    if (blockIdx.x == 0) g_e[s * 5 + i] = e;
                    if (s == 15) se15[i] = e;
                    mp[i] *= p.m[i];
                }
            }
            #pragma unroll
            for (int i = 0; i < 5; i++) sm16[i] = mp[i];
        }
    }

    const int b = blockIdx.x * 64 + tid;

    // prefetch warm d's and initial values
    const float* pdw = g_d + (unsigned)b;
    float wd[15];
    #pragma unroll
    for (int j = 0; j < WCH; j++)
        #pragma unroll
        for (int i = 0; i < 5; i++)
            wd[j * 5 + i] = pdw[(j * 6 + 1 + i) * B_LEN];
    const float gt0   = X[(size_t)b * (T_LEN * 7)];
    const float ta0   = X[(size_t)b * (T_LEN * 7) + 1];
    const float tzz47 = g_tzz[(unsigned)(47 * B_LEN + b)];

    // preload batch 0 (chunks 3..6)
    float buf[2][24];
    const float* pd = g_d + (unsigned)(WCH * 6 * B_LEN + b);
    #pragma unroll
    for (int q = 0; q < 24; q++) buf[0][q] = pd[q * B_LEN];

    __syncthreads();
    float A[36];
    #pragma unroll
    for (int i = 0; i < 36; i++) A[i] = sA[i];
    float m16[5], e15[5];
    #pragma unroll
    for (int i = 0; i < 5; i++) { m16[i] = sm16[i]; e15[i] = se15[i]; }

    // warm chunks (diagonal Tmid dynamics)
    float* pcs = g_cs + (unsigned)b;
    float tm[5];
    #pragma unroll
    for (int i = 0; i < 5; i++) tm[i] = fmaf(0.7f, gt0, 0.3f * ta0);
    float h47 = 0.f;
    #pragma unroll
    for (int j = 0; j < WCH; j++) {
        #pragma unroll
        for (int i = 0; i < 5; i++)
            pcs[(j * 6 + 1 + i) * B_LEN] = tm[i];
        if (j == WCH - 1) {
            h47 = e15[0] * tm[0];
            #pragma unroll
            for (int i = 1; i < 5; i++) h47 = fmaf(e15[i], tm[i], h47);
        }
        #pragma unroll
        for (int i = 0; i < 5; i++)
            tm[i] = fmaf(m16[i], tm[i], wd[j * 5 + i]);
    }
    float x[6];
    x[0] = tzz47 + h47;
    #pragma unroll
    for (int i = 0; i < 5; i++) x[1 + i] = tm[i];

    // 22 batches of 4 chunks (87 real + 1 pad; pad computed but never stored)
    pcs = g_cs + (unsigned)(WCH * 6 * B_LEN + b);
    #pragma unroll
    for (int batch = 0; batch < 22; batch++) {
        const int cu = batch & 1;
        if (batch < 21) {
            const float* pn = pd + (unsigned)(24 * B_LEN);
            #pragma unroll
            for (int q = 0; q < 24; q++) buf[cu ^ 1][q] = pn[q * B_LEN];
        }
        const int nc = (batch < 21) ? 4 : 3;
        #pragma unroll
        for (int c = 0; c < 4; c++) {
            const bool live = (c < nc);
            if (live) {
                #pragma unroll
                for (int k = 0; k < 6; k++) pcs[(c * 6 + k) * B_LEN] = x[k];
            }
            float y[6];
            #pragma unroll
            for (int i = 0; i < 6; i++) {
                float a = buf[cu][c * 6 + i];
                #pragma unroll
                for (int k = 0; k < 6; k++) a = fmaf(A[i * 6 + k], x[k], a);
                y[i] = a;
            }
            if (live) {
                #pragma unroll
                for (int k = 0; k < 6; k++) x[k] = y[k];
            }
        }
        pd  += (unsigned)(24 * B_LEN);
        pcs += (unsigned)(24 * B_LEN);
    }
}

// ---------------------------------------------------------------------------
// Emit: out[t] = tzz[t] + correction(chunk-start state). Fully parallel.
// Tables loaded from global (written by k_scan block 0).
// ---------------------------------------------------------------------------
__global__ __launch_bounds__(256) void k_emit(float* __restrict__ out)
{
    __shared__ float sm[32][33];
    __shared__ float s_r0p[17 * 6];
    __shared__ float s_e[16 * 5];
    const int tid = threadIdx.x;
    if (tid < 102) s_r0p[tid] = g_r0p[tid];
    if (tid < 80)  s_e[tid]   = g_e[tid];
    __syncthreads();

    const int b0 = blockIdx.x * 32;
    const int t0 = blockIdx.y * 32;
    const int lane = tid & 31;
    const int row  = tid >> 5;
    const int b = b0 + lane;
    const int tl0 = row * 4;
    const int jj = (t0 + tl0) >> 4;
    const bool warm = (jj < WCH);

    const float* pcs = g_cs + (unsigned)(jj * 6 * B_LEN + b);
    float cs[6];
    #pragma unroll
    for (int k = 0; k < 6; k++) cs[k] = pcs[k * B_LEN];

    const float* ptz = g_tzz + (unsigned)((t0 + tl0) * B_LEN + b);
    #pragma unroll
    for (int pp = 0; pp < 4; pp++) {
        const int s = (t0 + tl0 + pp) & 15;
        float v = ptz[pp * B_LEN];
        if (warm) {
            #pragma unroll
            for (int i = 0; i < 5; i++) v = fmaf(s_e[s * 5 + i], cs[1 + i], v);
        } else {
            #pragma unroll
            for (int k = 0; k < 6; k++) v = fmaf(s_r0p[(s + 1) * 6 + k], cs[k], v);
        }
        sm[tl0 + pp][lane] = v;
    }
    __syncthreads();
    #pragma unroll
    for (int pp = 0; pp < 4; pp++) {
        const int r = tl0 + pp;
        out[(unsigned)((b0 + r) * T_LEN + t0 + lane)] = sm[lane][r];
    }
}

extern "C" void kernel_launch(void* const* d_in, const int* in_sizes, int n_in,
                              void* d_out, int out_size) {
    const float* X          = (const float*)d_in[0];
    const float* rcR        = (const float*)d_in[1];
    const float* rcC        = (const float*)d_in[2];
    const float* winR       = (const float*)d_in[3];
    const float* hvac_gain  = (const float*)d_in[4];
    const float* W1         = (const float*)d_in[5];
    const float* B1         = (const float*)d_in[6];
    const float* W2         = (const float*)d_in[7];
    const float* B2         = (const float*)d_in[8];
    const float* int_gain   = (const float*)d_in[9];
    const float* direct_gain= (const float*)d_in[10];
    const float* abs_wall   = (const float*)d_in[11];
    const float* abs_roof   = (const float*)d_in[12];
    const float* zone_C_inv = (const float*)d_in[13];
    float* out = (float*)d_out;

    k_pre<<<1, 32>>>(rcR, rcC, winR, W1, B1, W2, B2,
                     int_gain, hvac_gain, direct_gain,
                     abs_wall, abs_roof, zone_C_inv);
    dim3 gA(B_LEN / 64, N_CH);
    kA<<<gA, 256>>>(X);
    k_scan<<<B_LEN / 64, 64>>>(X, rcR, rcC, winR, abs_wall, abs_roof,
                               zone_C_inv);
    dim3 ge(B_LEN / 32, T_LEN / 32);
    k_emit<<<ge, 256>>>(out);
}